// round 10
// baseline (speedup 1.0000x reference)
#include <cuda_runtime.h>
#include <cuda_bf16.h>
#include <cuda_pipeline.h>
#include <mma.h>
#include <math.h>

using namespace nvcuda;

#define BB 4
#define TF 4096
#define T1 2048
#define TE 1024
#define HID 320
#define NH 8
#define NKV 4
#define HD 40
#define FFN_D 1280
#define MTOK (BB * TE)
#define NFRM (BB * TF)

typedef __nv_bfloat16 bf16;

// ---------------- scratch (static device globals; no allocation) ----------------
__device__ bf16  g_xnp[NFRM * 256];
__device__ bf16  g_x0p[BB * TF * 960];
__device__ bf16  g_c1p[BB * T1 * 1920];
__device__ float g_x  [MTOK * HID];
__device__ float g_qkv[MTOK * 640];
__device__ bf16  g_h3  [MTOK * 960];
__device__ bf16  g_att3[MTOK * 960];
__device__ bf16  g_ffn3[MTOK * 3840];
__device__ bf16  g_linw3[320 * 256];
__device__ bf16  g_qkvw3[6 * 640 * 960];
__device__ bf16  g_ow3  [6 * 320 * 960];
__device__ bf16  g_fc1w3[6 * 1280 * 960];
__device__ bf16  g_fc2w3[6 * 320 * 3840];
__device__ bf16  g_w1p  [640 * 5 * 960];
__device__ bf16  g_w2p  [320 * 5 * 1920];

// ---------------- all GEMM weight splits in ONE launch ----------------
__global__ void prep_all_kernel(const float* __restrict__ qw, const float* __restrict__ kw,
                                const float* __restrict__ vw, const float* __restrict__ ow,
                                const float* __restrict__ f1w, const float* __restrict__ f2w,
                                const float* __restrict__ lw)
{
    int seg = blockIdx.y;
    if (seg == 6) {
        int i = blockIdx.x * 256 + threadIdx.x;
        if (i >= 320 * 80) return;
        int n = i / 80, k = i - n * 80;
        float w = lw[i];
        bf16 hi = __float2bfloat16_rn(w);
        bf16 lo = __float2bfloat16_rn(w - __bfloat162float(hi));
        bf16* dst = g_linw3 + (size_t)n * 256;
        dst[k] = hi;
        dst[80 + k] = hi;
        dst[160 + k] = lo;
        if (k < 16) dst[240 + k] = __float2bfloat16_rn(0.f);
        return;
    }
    const float* W;
    bf16* W3;
    int N, K;
    size_t stride;
    if      (seg == 0) { W = qw;  W3 = g_qkvw3;                      N = 320;  K = 320;  stride = (size_t)640 * 960; }
    else if (seg == 1) { W = kw;  W3 = g_qkvw3 + (size_t)320 * 960;  N = 160;  K = 320;  stride = (size_t)640 * 960; }
    else if (seg == 2) { W = vw;  W3 = g_qkvw3 + (size_t)480 * 960;  N = 160;  K = 320;  stride = (size_t)640 * 960; }
    else if (seg == 3) { W = ow;  W3 = g_ow3;                        N = 320;  K = 320;  stride = (size_t)320 * 960; }
    else if (seg == 4) { W = f1w; W3 = g_fc1w3;                      N = 1280; K = 320;  stride = (size_t)1280 * 960; }
    else               { W = f2w; W3 = g_fc2w3;                      N = 320;  K = 1280; stride = (size_t)320 * 3840; }
    int per = N * K;
    int i = blockIdx.x * 256 + threadIdx.x;
    if (i >= per * 6) return;
    int l = i / per, rem = i - l * per;
    int n = rem / K, k = rem - n * K;
    float w = W[i];
    bf16 hi = __float2bfloat16_rn(w);
    bf16 lo = __float2bfloat16_rn(w - __bfloat162float(hi));
    bf16* dst = W3 + (size_t)l * stride + (size_t)n * 3 * K;
    dst[k] = hi;
    dst[K + k] = hi;
    dst[2 * K + k] = lo;
}

// ---------------- conv weight split ----------------
__global__ void prep_conv_kernel(const float* __restrict__ W, bf16* __restrict__ Wp,
                                 int Co, int Ci)
{
    int i = blockIdx.x * 256 + threadIdx.x;
    if (i >= Co * Ci * 5) return;
    int o = i / (Ci * 5), rem = i - o * (Ci * 5);
    int ci = rem / 5, j = rem - ci * 5;
    float w = W[i];
    bf16 hi = __float2bfloat16_rn(w);
    bf16 lo = __float2bfloat16_rn(w - __bfloat162float(hi));
    int Ci3 = 3 * Ci;
    size_t d = ((size_t)o * 5 + j) * Ci3 + ci;
    Wp[d] = hi;
    Wp[d + Ci] = hi;
    Wp[d + 2 * Ci] = lo;
}

// ---------------- CMVN + asinh: one warp per frame -> packed [hi|lo|hi|0] ----------------
__global__ void __launch_bounds__(256) cmvn_kernel(const float* __restrict__ audio,
                                                   const float* __restrict__ log_k)
{
    int frame = (blockIdx.x * 256 + threadIdx.x) >> 5;
    int lane  = threadIdx.x & 31;
    if (frame >= NFRM) return;
    const float* src = audio + (size_t)frame * 80;
    float v0 = src[lane];
    float v1 = src[lane + 32];
    float v2 = (lane < 16) ? src[lane + 64] : 0.f;
    float s  = v0 + v1 + v2;
    float s2 = v0 * v0 + v1 * v1 + v2 * v2;
    #pragma unroll
    for (int off = 16; off; off >>= 1) {
        s  += __shfl_xor_sync(0xffffffffu, s,  off);
        s2 += __shfl_xor_sync(0xffffffffu, s2, off);
    }
    float m    = s * (1.f / 80.f);
    float var  = s2 * (1.f / 80.f) - m * m;
    float rinv = rsqrtf(var + 1e-6f);
    float ek   = expf(log_k[0]);
    size_t base = (size_t)frame * 256;
    float w0 = asinhf(ek * (v0 - m) * rinv);
    bf16 h0 = __float2bfloat16_rn(w0);
    bf16 l0 = __float2bfloat16_rn(w0 - __bfloat162float(h0));
    g_xnp[base + lane] = h0;
    g_xnp[base + 80 + lane] = l0;
    g_xnp[base + 160 + lane] = h0;
    float w1 = asinhf(ek * (v1 - m) * rinv);
    bf16 h1 = __float2bfloat16_rn(w1);
    bf16 l1 = __float2bfloat16_rn(w1 - __bfloat162float(h1));
    g_xnp[base + lane + 32] = h1;
    g_xnp[base + 112 + lane] = l1;
    g_xnp[base + 192 + lane] = h1;
    if (lane < 16) {
        float w2 = asinhf(ek * (v2 - m) * rinv);
        bf16 h2 = __float2bfloat16_rn(w2);
        bf16 l2 = __float2bfloat16_rn(w2 - __bfloat162float(h2));
        g_xnp[base + lane + 64] = h2;
        g_xnp[base + 144 + lane] = l2;
        g_xnp[base + 224 + lane] = h2;
        g_xnp[base + 240 + lane] = __float2bfloat16_rn(0.f);
    }
}

// ---------------- LayerNorm (fp32 out) ----------------
__global__ void ln_kernel(const float* __restrict__ x, const float* __restrict__ w,
                          float* __restrict__ y)
{
    int t = blockIdx.x;
    int c = threadIdx.x;
    float v = x[(size_t)t * HID + c];
    float s = v, s2 = v * v;
    #pragma unroll
    for (int off = 16; off; off >>= 1) {
        s  += __shfl_down_sync(0xffffffffu, s,  off);
        s2 += __shfl_down_sync(0xffffffffu, s2, off);
    }
    __shared__ float ss[10], ss2[10];
    __shared__ float mean_s, rstd_s;
    int wid = c >> 5, lane = c & 31;
    if (lane == 0) { ss[wid] = s; ss2[wid] = s2; }
    __syncthreads();
    if (c == 0) {
        float ts = 0.f, ts2 = 0.f;
        #pragma unroll
        for (int i = 0; i < 10; i++) { ts += ss[i]; ts2 += ss2[i]; }
        float mean = ts * (1.f / 320.f);
        float var  = ts2 * (1.f / 320.f) - mean * mean;
        mean_s = mean;
        rstd_s = rsqrtf(var + 1e-5f);
    }
    __syncthreads();
    y[(size_t)t * HID + c] = (v - mean_s) * rstd_s * w[c];
}

// ---------------- LayerNorm with packed bf16 split output [hi|lo|hi] ----------------
__global__ void ln_pack_kernel(const float* __restrict__ x, const float* __restrict__ w,
                               bf16* __restrict__ y3)
{
    int t = blockIdx.x;
    int c = threadIdx.x;
    float v = x[(size_t)t * HID + c];
    float s = v, s2 = v * v;
    #pragma unroll
    for (int off = 16; off; off >>= 1) {
        s  += __shfl_down_sync(0xffffffffu, s,  off);
        s2 += __shfl_down_sync(0xffffffffu, s2, off);
    }
    __shared__ float ss[10], ss2[10];
    __shared__ float mean_s, rstd_s;
    int wid = c >> 5, lane = c & 31;
    if (lane == 0) { ss[wid] = s; ss2[wid] = s2; }
    __syncthreads();
    if (c == 0) {
        float ts = 0.f, ts2 = 0.f;
        #pragma unroll
        for (int i = 0; i < 10; i++) { ts += ss[i]; ts2 += ss2[i]; }
        float mean = ts * (1.f / 320.f);
        float var  = ts2 * (1.f / 320.f) - mean * mean;
        mean_s = mean;
        rstd_s = rsqrtf(var + 1e-5f);
    }
    __syncthreads();
    float yv = (v - mean_s) * rstd_s * w[c];
    bf16 hi = __float2bfloat16_rn(yv);
    bf16 lo = __float2bfloat16_rn(yv - __bfloat162float(hi));
    size_t base = (size_t)t * 960;
    y3[base + c] = hi;
    y3[base + 320 + c] = lo;
    y3[base + 640 + c] = hi;
}

// ======================= wmma common =======================
#define LDA 40
#define ST_A 5120
#define ST_ELEMS 7680
#define SMEM_BYTES 46080
// M64 variant
#define ST64_A 2560
#define ST64_ELEMS 5120
#define SMEM64_BYTES 30720

__device__ __forceinline__ void g_load(const bf16* A3, const bf16* B3,
                                       bf16* As, bf16* Bs,
                                       int tid, int m0, int n0, int K3, int k0)
{
    #pragma unroll
    for (int i = 0; i < 4; i++) {
        int id = tid + i * 128;
        int r = id >> 2, c = id & 3;
        __pipeline_memcpy_async(As + r * LDA + c * 8,
                                A3 + (size_t)(m0 + r) * K3 + k0 + c * 8, 16);
    }
    #pragma unroll
    for (int i = 0; i < 2; i++) {
        int id = tid + i * 128;
        int r = id >> 2, c = id & 3;
        __pipeline_memcpy_async(Bs + r * LDA + c * 8,
                                B3 + (size_t)(n0 + r) * K3 + k0 + c * 8, 16);
    }
    __pipeline_commit();
}

__device__ __forceinline__ void g_load64(const bf16* A3, const bf16* B3,
                                         bf16* As, bf16* Bs,
                                         int tid, int m0, int n0, int K3, int k0)
{
    #pragma unroll
    for (int i = 0; i < 2; i++) {
        int id = tid + i * 128;
        int r = id >> 2, c = id & 3;
        __pipeline_memcpy_async(As + r * LDA + c * 8,
                                A3 + (size_t)(m0 + r) * K3 + k0 + c * 8, 16);
    }
    #pragma unroll
    for (int i = 0; i < 2; i++) {
        int id = tid + i * 128;
        int r = id >> 2, c = id & 3;
        __pipeline_memcpy_async(Bs + r * LDA + c * 8,
                                B3 + (size_t)(n0 + r) * K3 + k0 + c * 8, 16);
    }
    __pipeline_commit();
}

__device__ __forceinline__ void c_load(const bf16* Ap, const bf16* Wp,
                                       bf16* As, bf16* Bs,
                                       int tid, int inbase, int t0, int tap,
                                       int n0, int Ci3, int k0)
{
    #pragma unroll
    for (int i = 0; i < 4; i++) {
        int id = tid + i * 128;
        int r = id >> 2, c = id & 3;
        int tau = 2 * (t0 + r) - 4 + tap;
        bf16* adst = As + r * LDA + c * 8;
        if (tau >= 0) {
            __pipeline_memcpy_async(adst, Ap + (size_t)(inbase + tau) * Ci3 + k0 + c * 8, 16);
        } else {
            *(uint4*)adst = make_uint4(0u, 0u, 0u, 0u);
        }
    }
    #pragma unroll
    for (int i = 0; i < 2; i++) {
        int id = tid + i * 128;
        int r = id >> 2, c = id & 3;
        __pipeline_memcpy_async(Bs + r * LDA + c * 8,
                                Wp + ((size_t)(n0 + r) * 5 + tap) * Ci3 + k0 + c * 8, 16);
    }
    __pipeline_commit();
}

__device__ __forceinline__ void c_load64(const bf16* Ap, const bf16* Wp,
                                         bf16* As, bf16* Bs,
                                         int tid, int inbase, int t0, int tap,
                                         int n0, int Ci3, int k0)
{
    #pragma unroll
    for (int i = 0; i < 2; i++) {
        int id = tid + i * 128;
        int r = id >> 2, c = id & 3;
        int tau = 2 * (t0 + r) - 4 + tap;
        bf16* adst = As + r * LDA + c * 8;
        if (tau >= 0) {
            __pipeline_memcpy_async(adst, Ap + (size_t)(inbase + tau) * Ci3 + k0 + c * 8, 16);
        } else {
            *(uint4*)adst = make_uint4(0u, 0u, 0u, 0u);
        }
    }
    #pragma unroll
    for (int i = 0; i < 2; i++) {
        int id = tid + i * 128;
        int r = id >> 2, c = id & 3;
        __pipeline_memcpy_async(Bs + r * LDA + c * 8,
                                Wp + ((size_t)(n0 + r) * 5 + tap) * Ci3 + k0 + c * 8, 16);
    }
    __pipeline_commit();
}

// ---------------- wmma GEMM, 128x64 tile (4 warps x 32x64) ----------------
template<int ACT, int BETA, int PACK>
__global__ void __launch_bounds__(128) wmma_gemm_kernel(
    const bf16* __restrict__ A3, const bf16* __restrict__ B3,
    float* __restrict__ C, bf16* __restrict__ P,
    int M, int N, int K3, int ldc, int packK)
{
    __shared__ __align__(16) char smem_raw[SMEM_BYTES];
    float* Cs = (float*)smem_raw;

    int tid = threadIdx.x;
    int w = tid >> 5;
    int m0 = blockIdx.y * 128;
    int n0 = blockIdx.x * 64;

    wmma::fragment<wmma::accumulator, 16, 16, 16, float> cfrag[2][4];
    #pragma unroll
    for (int mi = 0; mi < 2; mi++)
        #pragma unroll
        for (int nj = 0; nj < 4; nj++)
            wmma::fill_fragment(cfrag[mi][nj], 0.f);

    int nk = K3 / 32;
    {
        bf16* As0 = (bf16*)smem_raw;
        g_load(A3, B3, As0, As0 + ST_A, tid, m0, n0, K3, 0);
        bf16* As1 = (bf16*)smem_raw + ST_ELEMS;
        if (nk > 1) g_load(A3, B3, As1, As1 + ST_A, tid, m0, n0, K3, 32);
        else        __pipeline_commit();
    }
    int st = 0;
    for (int kt = 0; kt < nk; kt++) {
        __pipeline_wait_prior(1);
        __syncthreads();
        bf16* Asc = (bf16*)smem_raw + st * ST_ELEMS;
        bf16* Bsc = Asc + ST_A;
        #pragma unroll
        for (int kk = 0; kk < 32; kk += 16) {
            wmma::fragment<wmma::matrix_a, 16, 16, 16, bf16, wmma::row_major> afrag[2];
            wmma::fragment<wmma::matrix_b, 16, 16, 16, bf16, wmma::col_major> bfrag[4];
            #pragma unroll
            for (int mi = 0; mi < 2; mi++)
                wmma::load_matrix_sync(afrag[mi], Asc + (w * 32 + mi * 16) * LDA + kk, LDA);
            #pragma unroll
            for (int nj = 0; nj < 4; nj++)
                wmma::load_matrix_sync(bfrag[nj], Bsc + (nj * 16) * LDA + kk, LDA);
            #pragma unroll
            for (int mi = 0; mi < 2; mi++)
                #pragma unroll
                for (int nj = 0; nj < 4; nj++)
                    wmma::mma_sync(cfrag[mi][nj], afrag[mi], bfrag[nj], cfrag[mi][nj]);
        }
        if (kt + 2 < nk) {
            int ns = kt + 2 - ((kt + 2) / 3) * 3;
            bf16* Asn = (bf16*)smem_raw + ns * ST_ELEMS;
            g_load(A3, B3, Asn, Asn + ST_A, tid, m0, n0, K3, (kt + 2) * 32);
        } else {
            __pipeline_commit();
        }
        st++; if (st == 3) st = 0;
    }
    __syncthreads();

    #pragma unroll
    for (int mi = 0; mi < 2; mi++)
        #pragma unroll
        for (int nj = 0; nj < 4; nj++)
            wmma::store_matrix_sync(Cs + (w * 32 + mi * 16) * 64 + nj * 16,
                                    cfrag[mi][nj], 64, wmma::mem_row_major);
    __syncthreads();

    #pragma unroll
    for (int it = 0; it < 16; it++) {
        int idx = it * 512 + tid * 4;
        int m = idx >> 6, n = idx & 63;
        float4 v4 = *(float4*)(Cs + idx);
        float vv[4] = {v4.x, v4.y, v4.z, v4.w};
        if (BETA) {
            float4 c4 = *(const float4*)(C + (size_t)(m0 + m) * ldc + n0 + n);
            vv[0] += c4.x; vv[1] += c4.y; vv[2] += c4.z; vv[3] += c4.w;
        }
        if (ACT) {
            #pragma unroll
            for (int j = 0; j < 4; j++) vv[j] = vv[j] / (1.f + __expf(-vv[j]));
        }
        if (PACK) {
            size_t base = (size_t)(m0 + m) * 3 * packK + n0 + n;
            #pragma unroll
            for (int j = 0; j < 4; j++) {
                bf16 hi = __float2bfloat16_rn(vv[j]);
                bf16 lo = __float2bfloat16_rn(vv[j] - __bfloat162float(hi));
                P[base + j] = hi;
                P[base + packK + j] = lo;
                P[base + 2 * packK + j] = hi;
            }
        } else {
            float4 o4;
            o4.x = vv[0]; o4.y = vv[1]; o4.z = vv[2]; o4.w = vv[3];
            *(float4*)(C + (size_t)(m0 + m) * ldc + n0 + n) = o4;
        }
    }
}

// ---------------- wmma GEMM, 64x64 tile (4 warps x 16x64) — for small-grid GEMMs --------
template<int ACT, int BETA, int PACK>
__global__ void __launch_bounds__(128) wmma_gemm64_kernel(
    const bf16* __restrict__ A3, const bf16* __restrict__ B3,
    float* __restrict__ C, bf16* __restrict__ P,
    int M, int N, int K3, int ldc, int packK)
{
    __shared__ __align__(16) char smem_raw[SMEM64_BYTES];
    float* Cs = (float*)smem_raw;

    int tid = threadIdx.x;
    int w = tid >> 5;
    int m0 = blockIdx.y * 64;
    int n0 = blockIdx.x * 64;

    wmma::fragment<wmma::accumulator, 16, 16, 16, float> cfrag[4];
    #pragma unroll
    for (int nj = 0; nj < 4; nj++)
        wmma::fill_fragment(cfrag[nj], 0.f);

    int nk = K3 / 32;
    {
        bf16* As0 = (bf16*)smem_raw;
        g_load64(A3, B3, As0, As0 + ST64_A, tid, m0, n0, K3, 0);
        bf16* As1 = (bf16*)smem_raw + ST64_ELEMS;
        if (nk > 1) g_load64(A3, B3, As1, As1 + ST64_A, tid, m0, n0, K3, 32);
        else        __pipeline_commit();
    }
    int st = 0;
    for (int kt = 0; kt < nk; kt++) {
        __pipeline_wait_prior(1);
        __syncthreads();
        bf16* Asc = (bf16*)smem_raw + st * ST64_ELEMS;
        bf16* Bsc = Asc + ST64_A;
        #pragma unroll
        for (int kk = 0; kk < 32; kk += 16) {
            wmma::fragment<wmma::matrix_a, 16, 16, 16, bf16, wmma::row_major> afrag;
            wmma::fragment<wmma::matrix_b, 16, 16, 16, bf16, wmma::col_major> bfrag[4];
            wmma::load_matrix_sync(afrag, Asc + (w * 16) * LDA + kk, LDA);
            #pragma unroll
            for (int nj = 0; nj < 4; nj++)
                wmma::load_matrix_sync(bfrag[nj], Bsc + (nj * 16) * LDA + kk, LDA);
            #pragma unroll
            for (int nj = 0; nj < 4; nj++)
                wmma::mma_sync(cfrag[nj], afrag, bfrag[nj], cfrag[nj]);
        }
        if (kt + 2 < nk) {
            int ns = kt + 2 - ((kt + 2) / 3) * 3;
            bf16* Asn = (bf16*)smem_raw + ns * ST64_ELEMS;
            g_load64(A3, B3, Asn, Asn + ST64_A, tid, m0, n0, K3, (kt + 2) * 32);
        } else {
            __pipeline_commit();
        }
        st++; if (st == 3) st = 0;
    }
    __syncthreads();

    #pragma unroll
    for (int nj = 0; nj < 4; nj++)
        wmma::store_matrix_sync(Cs + (w * 16) * 64 + nj * 16, cfrag[nj], 64,
                                wmma::mem_row_major);
    __syncthreads();

    #pragma unroll
    for (int it = 0; it < 8; it++) {
        int idx = it * 512 + tid * 4;
        int m = idx >> 6, n = idx & 63;
        float4 v4 = *(float4*)(Cs + idx);
        float vv[4] = {v4.x, v4.y, v4.z, v4.w};
        if (BETA) {
            float4 c4 = *(const float4*)(C + (size_t)(m0 + m) * ldc + n0 + n);
            vv[0] += c4.x; vv[1] += c4.y; vv[2] += c4.z; vv[3] += c4.w;
        }
        if (ACT) {
            #pragma unroll
            for (int j = 0; j < 4; j++) vv[j] = vv[j] / (1.f + __expf(-vv[j]));
        }
        if (PACK) {
            size_t base = (size_t)(m0 + m) * 3 * packK + n0 + n;
            #pragma unroll
            for (int j = 0; j < 4; j++) {
                bf16 hi = __float2bfloat16_rn(vv[j]);
                bf16 lo = __float2bfloat16_rn(vv[j] - __bfloat162float(hi));
                P[base + j] = hi;
                P[base + packK + j] = lo;
                P[base + 2 * packK + j] = hi;
            }
        } else {
            float4 o4;
            o4.x = vv[0]; o4.y = vv[1]; o4.z = vv[2]; o4.w = vv[3];
            *(float4*)(C + (size_t)(m0 + m) * ldc + n0 + n) = o4;
        }
    }
}

// ---------------- wmma conv, 128-row tile ----------------
template<int ACT, int PACK>
__global__ void __launch_bounds__(128) wmma_conv_kernel(
    const bf16* __restrict__ Ap, const bf16* __restrict__ Wp,
    const float* __restrict__ bias,
    float* __restrict__ Cout, bf16* __restrict__ P,
    int Tin, int Tout, int Ci3, int Co, int packK)
{
    __shared__ __align__(16) char smem_raw[SMEM_BYTES];
    float* Cs = (float*)smem_raw;

    int tid = threadIdx.x;
    int w = tid >> 5;
    int tpb = Tout / 128;
    int b  = blockIdx.y / tpb;
    int t0 = (blockIdx.y % tpb) * 128;
    int n0 = blockIdx.x * 64;
    int inbase = b * Tin;

    wmma::fragment<wmma::accumulator, 16, 16, 16, float> cfrag[2][4];
    #pragma unroll
    for (int mi = 0; mi < 2; mi++)
        #pragma unroll
        for (int nj = 0; nj < 4; nj++)
            wmma::fill_fragment(cfrag[mi][nj], 0.f);

    int cpt = Ci3 / 32;
    int niter = 5 * cpt;
    {
        bf16* As0 = (bf16*)smem_raw;
        c_load(Ap, Wp, As0, As0 + ST_A, tid, inbase, t0, 0, n0, Ci3, 0);
        bf16* As1 = (bf16*)smem_raw + ST_ELEMS;
        int tap1 = 1 / cpt, k01 = (1 % cpt) * 32;
        if (niter > 1) c_load(Ap, Wp, As1, As1 + ST_A, tid, inbase, t0, tap1, n0, Ci3, k01);
        else           __pipeline_commit();
    }
    int st = 0;
    for (int it = 0; it < niter; it++) {
        __pipeline_wait_prior(1);
        __syncthreads();
        bf16* Asc = (bf16*)smem_raw + st * ST_ELEMS;
        bf16* Bsc = Asc + ST_A;
        #pragma unroll
        for (int kk = 0; kk < 32; kk += 16) {
            wmma::fragment<wmma::matrix_a, 16, 16, 16, bf16, wmma::row_major> afrag[2];
            wmma::fragment<wmma::matrix_b, 16, 16, 16, bf16, wmma::col_major> bfrag[4];
            #pragma unroll
            for (int mi = 0; mi < 2; mi++)
                wmma::load_matrix_sync(afrag[mi], Asc + (w * 32 + mi * 16) * LDA + kk, LDA);
            #pragma unroll
            for (int nj = 0; nj < 4; nj++)
                wmma::load_matrix_sync(bfrag[nj], Bsc + (nj * 16) * LDA + kk, LDA);
            #pragma unroll
            for (int mi = 0; mi < 2; mi++)
                #pragma unroll
                for (int nj = 0; nj < 4; nj++)
                    wmma::mma_sync(cfrag[mi][nj], afrag[mi], bfrag[nj], cfrag[mi][nj]);
        }
        if (it + 2 < niter) {
            int nxt = it + 2;
            int ns = nxt - (nxt / 3) * 3;
            int tap = nxt / cpt;
            int k0  = (nxt - tap * cpt) * 32;
            bf16* Asn = (bf16*)smem_raw + ns * ST_ELEMS;
            c_load(Ap, Wp, Asn, Asn + ST_A, tid, inbase, t0, tap, n0, Ci3, k0);
        } else {
            __pipeline_commit();
        }
        st++; if (st == 3) st = 0;
    }
    __syncthreads();

    #pragma unroll
    for (int mi = 0; mi < 2; mi++)
        #pragma unroll
        for (int nj = 0; nj < 4; nj++)
            wmma::store_matrix_sync(Cs + (w * 32 + mi * 16) * 64 + nj * 16,
                                    cfrag[mi][nj], 64, wmma::mem_row_major);
    __syncthreads();

    #pragma unroll
    for (int it = 0; it < 16; it++) {
        int idx = it * 512 + tid * 4;
        int m = idx >> 6, n = idx & 63;
        int orow = b * Tout + t0 + m;
        float4 v4 = *(float4*)(Cs + idx);
        float vv[4] = {v4.x, v4.y, v4.z, v4.w};
        #pragma unroll
        for (int j = 0; j < 4; j++) vv[j] += bias[n0 + n + j];
        if (ACT) {
            #pragma unroll
            for (int j = 0; j < 4; j++) vv[j] = vv[j] / (1.f + __expf(-vv[j]));
        }
        if (PACK) {
            size_t base = (size_t)orow * 3 * packK + n0 + n;
            #pragma unroll
            for (int j = 0; j < 4; j++) {
                bf16 hi = __float2bfloat16_rn(vv[j]);
                bf16 lo = __float2bfloat16_rn(vv[j] - __bfloat162float(hi));
                P[base + j] = hi;
                P[base + packK + j] = lo;
                P[base + 2 * packK + j] = hi;
            }
        } else {
            float4 o4;
            o4.x = vv[0]; o4.y = vv[1]; o4.z = vv[2]; o4.w = vv[3];
            *(float4*)(Cout + (size_t)orow * Co + n0 + n) = o4;
        }
    }
}

// ---------------- wmma conv, 64-row tile (for conv2's small grid) ----------------
template<int ACT, int PACK>
__global__ void __launch_bounds__(128) wmma_conv64_kernel(
    const bf16* __restrict__ Ap, const bf16* __restrict__ Wp,
    const float* __restrict__ bias,
    float* __restrict__ Cout, bf16* __restrict__ P,
    int Tin, int Tout, int Ci3, int Co, int packK)
{
    __shared__ __align__(16) char smem_raw[SMEM64_BYTES];
    float* Cs = (float*)smem_raw;

    int tid = threadIdx.x;
    int w = tid >> 5;
    int tpb = Tout / 64;
    int b  = blockIdx.y / tpb;
    int t0 = (blockIdx.y % tpb) * 64;
    int n0 = blockIdx.x * 64;
    int inbase = b * Tin;

    wmma::fragment<wmma::accumulator, 16, 16, 16, float> cfrag[4];
    #pragma unroll
    for (int nj = 0; nj < 4; nj++)
        wmma::fill_fragment(cfrag[nj], 0.f);

    int cpt = Ci3 / 32;
    int niter = 5 * cpt;
    {
        bf16* As0 = (bf16*)smem_raw;
        c_load64(Ap, Wp, As0, As0 + ST64_A, tid, inbase, t0, 0, n0, Ci3, 0);
        bf16* As1 = (bf16*)smem_raw + ST64_ELEMS;
        int tap1 = 1 / cpt, k01 = (1 % cpt) * 32;
        if (niter > 1) c_load64(Ap, Wp, As1, As1 + ST64_A, tid, inbase, t0, tap1, n0, Ci3, k01);
        else           __pipeline_commit();
    }
    int st = 0;
    for (int it = 0; it < niter; it++) {
        __pipeline_wait_prior(1);
        __syncthreads();
        bf16* Asc = (bf16*)smem_raw + st * ST64_ELEMS;
        bf16* Bsc = Asc + ST64_A;
        #pragma unroll
        for (int kk = 0; kk < 32; kk += 16) {
            wmma::fragment<wmma::matrix_a, 16, 16, 16, bf16, wmma::row_major> afrag;
            wmma::fragment<wmma::matrix_b, 16, 16, 16, bf16, wmma::col_major> bfrag[4];
            wmma::load_matrix_sync(afrag, Asc + (w * 16) * LDA + kk, LDA);
            #pragma unroll
            for (int nj = 0; nj < 4; nj++)
                wmma::load_matrix_sync(bfrag[nj], Bsc + (nj * 16) * LDA + kk, LDA);
            #pragma unroll
            for (int nj = 0; nj < 4; nj++)
                wmma::mma_sync(cfrag[nj], afrag, bfrag[nj], cfrag[nj]);
        }
        if (it + 2 < niter) {
            int nxt = it + 2;
            int ns = nxt - (nxt / 3) * 3;
            int tap = nxt / cpt;
            int k0  = (nxt - tap * cpt) * 32;
            bf16* Asn = (bf16*)smem_raw + ns * ST64_ELEMS;
            c_load64(Ap, Wp, Asn, Asn + ST64_A, tid, inbase, t0, tap, n0, Ci3, k0);
        } else {
            __pipeline_commit();
        }
        st++; if (st == 3) st = 0;
    }
    __syncthreads();

    #pragma unroll
    for (int nj = 0; nj < 4; nj++)
        wmma::store_matrix_sync(Cs + (w * 16) * 64 + nj * 16, cfrag[nj], 64,
                                wmma::mem_row_major);
    __syncthreads();

    #pragma unroll
    for (int it = 0; it < 8; it++) {
        int idx = it * 512 + tid * 4;
        int m = idx >> 6, n = idx & 63;
        int orow = b * Tout + t0 + m;
        float4 v4 = *(float4*)(Cs + idx);
        float vv[4] = {v4.x, v4.y, v4.z, v4.w};
        #pragma unroll
        for (int j = 0; j < 4; j++) vv[j] += bias[n0 + n + j];
        if (ACT) {
            #pragma unroll
            for (int j = 0; j < 4; j++) vv[j] = vv[j] / (1.f + __expf(-vv[j]));
        }
        if (PACK) {
            size_t base = (size_t)orow * 3 * packK + n0 + n;
            #pragma unroll
            for (int j = 0; j < 4; j++) {
                bf16 hi = __float2bfloat16_rn(vv[j]);
                bf16 lo = __float2bfloat16_rn(vv[j] - __bfloat162float(hi));
                P[base + j] = hi;
                P[base + packK + j] = lo;
                P[base + 2 * packK + j] = hi;
            }
        } else {
            float4 o4;
            o4.x = vv[0]; o4.y = vv[1]; o4.z = vv[2]; o4.w = vv[3];
            *(float4*)(Cout + (size_t)orow * Co + n0 + n) = o4;
        }
    }
}

// ---------------- attention: smem-tiled, block = 8 heads x 16 queries ----------------
__global__ void __launch_bounds__(128) attn_kernel(int rw)
{
    __shared__ float kv[36 * 320];
    int t0 = blockIdx.x * 16;
    int b  = blockIdx.y;
    int tid = threadIdx.x;

    for (int idx = tid; idx < 36 * 320; idx += 128) {
        int row = idx / 320, col = idx - (idx / 320) * 320;
        int k = t0 - 15 + row;
        float v = 0.f;
        if (k >= 0 && k < TE)
            v = g_qkv[((size_t)b * TE + k) * 640 + 320 + col];
        kv[idx] = v;
    }
    __syncthreads();

    int h  = tid >> 4;
    int qi = tid & 15;
    int tq = t0 + qi;
    int kvh = h >> 1;
    const float* qp = g_qkv + ((size_t)b * TE + tq) * 640 + h * HD;
    float qv[HD];
    #pragma unroll
    for (int d = 0; d < HD; d++) qv[d] = qp[d];

    int k0 = tq - 15; if (k0 < 0) k0 = 0;
    int k1 = tq + (rw > 0 ? rw - 1 : 0); if (k1 > TE - 1) k1 = TE - 1;
    float m = -1e30f, l = 0.f;
    float acc[HD];
    #pragma unroll
    for (int d = 0; d < HD; d++) acc[d] = 0.f;
    const float scale = 0.15811388300841897f;

    for (int k = k0; k <= k1; k++) {
        const float* kp = kv + (k - (t0 - 15)) * 320 + kvh * HD;
        float s = 0.f;
        #pragma unroll
        for (int d = 0; d < HD; d++) s += qv[d] * kp[d];
        s *= scale;
        float nm = fmaxf(m, s);
        float f  = __expf(m - nm);
        float p  = __expf(s - nm);
        m = nm;
        l = l * f + p;
        const float* vp = kp + 160;
        #pragma unroll
        for (int d = 0; d < HD; d++) acc[d] = acc[d] * f + p * vp[d];
    }
    float rl = 1.f / l;
    size_t base = ((size_t)b * TE + tq) * 960 + h * HD;
    #pragma unroll
    for (int d = 0; d < HD; d++) {
        float v = acc[d] * rl;
        bf16 hi = __float2bfloat16_rn(v);
        bf16 lo = __float2bfloat16_rn(v - __bfloat162float(hi));
        g_att3[base + d] = hi;
        g_att3[base + 320 + d] = lo;
        g_att3[base + 640 + d] = hi;
    }
}

// ---------------- launch ----------------
extern "C" void kernel_launch(void* const* d_in, const int* in_sizes, int n_in,
                              void* d_out, int out_size)
{
    const float* audio   = (const float*)d_in[0];
    const float* log_k   = (const float*)d_in[2];
    const float* lin_w   = (const float*)d_in[3];
    const float* conv1_w = (const float*)d_in[4];
    const float* conv1_b = (const float*)d_in[5];
    const float* conv2_w = (const float*)d_in[6];
    const float* conv2_b = (const float*)d_in[7];
    const float* ln1_w   = (const float*)d_in[8];
    const float* q_w     = (const float*)d_in[9];
    const float* k_w     = (const float*)d_in[10];
    const float* v_w     = (const float*)d_in[11];
    const float* o_w     = (const float*)d_in[12];
    const float* ln2_w   = (const float*)d_in[13];
    const float* fc1_w   = (const float*)d_in[14];
    const float* fc2_w   = (const float*)d_in[15];
    const float* fln_w   = (const float*)d_in[16];

    bf16 *pxnp, *px0p, *pc1p, *ph3, *patt3, *pffn3, *plinw3, *pqkvw3, *pow3, *pfc1w3, *pfc2w3, *pw1p, *pw2p;
    float *px, *pqkv;
    cudaGetSymbolAddress((void**)&pxnp,   g_xnp);
    cudaGetSymbolAddress((void**)&px0p,   g_x0p);
    cudaGetSymbolAddress((void**)&pc1p,   g_c1p);
    cudaGetSymbolAddress((void**)&px,     g_x);
    cudaGetSymbolAddress((void**)&pqkv,   g_qkv);
    cudaGetSymbolAddress((void**)&ph3,    g_h3);
    cudaGetSymbolAddress((void**)&patt3,  g_att3);
    cudaGetSymbolAddress((void**)&pffn3,  g_ffn3);
    cudaGetSymbolAddress((void**)&plinw3, g_linw3);
    cudaGetSymbolAddress((void**)&pqkvw3, g_qkvw3);
    cudaGetSymbolAddress((void**)&pow3,   g_ow3);
    cudaGetSymbolAddress((void**)&pfc1w3, g_fc1w3);
    cudaGetSymbolAddress((void**)&pfc2w3, g_fc2w3);
    cudaGetSymbolAddress((void**)&pw1p,   g_w1p);
    cudaGetSymbolAddress((void**)&pw2p,   g_w2p);

    float* nullC = 0;
    bf16*  nullP = 0;

    prep_all_kernel<<<dim3(9600, 7), 256>>>(q_w, k_w, v_w, o_w, fc1_w, fc2_w, lin_w);
    prep_conv_kernel<<<(640 * 320 * 5 + 255) / 256, 256>>>(conv1_w, pw1p, 640, 320);
    prep_conv_kernel<<<(320 * 640 * 5 + 255) / 256, 256>>>(conv2_w, pw2p, 320, 640);
    cmvn_kernel<<<NFRM / 8, 256>>>(audio, log_k);
    wmma_gemm_kernel<1, 0, 1><<<dim3(320 / 64, NFRM / 128), 128>>>(
        pxnp, plinw3, nullC, px0p, NFRM, 320, 256, 0, 320);
    wmma_conv_kernel<1, 1><<<dim3(640 / 64, (T1 / 128) * BB), 128>>>(
        px0p, pw1p, conv1_b, nullC, pc1p, TF, T1, 960, 640, 640);
    wmma_conv64_kernel<0, 0><<<dim3(320 / 64, (TE / 64) * BB), 128>>>(
        pc1p, pw2p, conv2_b, px, nullP, T1, TE, 1920, 320, 0);

    const int M = MTOK;
    static const int rws[6] = {4, 4, 0, 0, 4, 4};
    for (int i = 0; i < 6; i++) {
        ln_pack_kernel<<<M, HID>>>(px, ln1_w + (size_t)i * HID, ph3);
        wmma_gemm64_kernel<0, 0, 0><<<dim3(640 / 64, M / 64), 128>>>(
            ph3, pqkvw3 + (size_t)i * 640 * 960, pqkv, nullP, M, 640, 960, 640, 0);
        attn_kernel<<<dim3(TE / 16, BB), 128>>>(rws[i]);
        wmma_gemm64_kernel<0, 1, 0><<<dim3(320 / 64, M / 64), 128>>>(
            patt3, pow3 + (size_t)i * 320 * 960, px, nullP, M, 320, 960, 320, 0);
        ln_pack_kernel<<<M, HID>>>(px, ln2_w + (size_t)i * HID, ph3);
        wmma_gemm_kernel<1, 0, 1><<<dim3(1280 / 64, M / 128), 128>>>(
            ph3, pfc1w3 + (size_t)i * 1280 * 960, nullC, pffn3, M, 1280, 960, 0, 1280);
        wmma_gemm64_kernel<0, 1, 0><<<dim3(320 / 64, M / 64), 128>>>(
            pffn3, pfc2w3 + (size_t)i * 320 * 3840, px, nullP, M, 320, 3840, 320, 0);
    }
    ln_kernel<<<M, HID>>>(px, fln_w, (float*)d_out);
}

// round 11
// speedup vs baseline: 1.1020x; 1.1020x over previous
#include <cuda_runtime.h>
#include <cuda_bf16.h>
#include <cuda_pipeline.h>
#include <mma.h>
#include <math.h>

using namespace nvcuda;

#define BB 4
#define TF 4096
#define T1 2048
#define TE 1024
#define HID 320
#define NH 8
#define NKV 4
#define HD 40
#define FFN_D 1280
#define MTOK (BB * TE)
#define NFRM (BB * TF)

typedef __nv_bfloat16 bf16;

// ---------------- scratch (static device globals; no allocation) ----------------
__device__ bf16  g_xnp[NFRM * 256];
__device__ bf16  g_x0p[BB * TF * 960];
__device__ bf16  g_c1p[BB * T1 * 1920];
__device__ float g_x  [MTOK * HID];
__device__ float g_qkv[MTOK * 640];
__device__ float g_part[4 * MTOK * 640];        // split-K partials (max 4 x M x 640)
__device__ bf16  g_h3  [MTOK * 960];
__device__ bf16  g_att3[MTOK * 960];
__device__ bf16  g_ffn3[MTOK * 3840];
__device__ bf16  g_linw3[320 * 256];
__device__ bf16  g_qkvw3[6 * 640 * 960];
__device__ bf16  g_ow3  [6 * 320 * 960];
__device__ bf16  g_fc1w3[6 * 1280 * 960];
__device__ bf16  g_fc2w3[6 * 320 * 3840];
__device__ bf16  g_w1p  [640 * 5 * 960];
__device__ bf16  g_w2p  [320 * 5 * 1920];

// ---------------- all GEMM weight splits in ONE launch ----------------
__global__ void prep_all_kernel(const float* __restrict__ qw, const float* __restrict__ kw,
                                const float* __restrict__ vw, const float* __restrict__ ow,
                                const float* __restrict__ f1w, const float* __restrict__ f2w,
                                const float* __restrict__ lw)
{
    int seg = blockIdx.y;
    if (seg == 6) {
        int i = blockIdx.x * 256 + threadIdx.x;
        if (i >= 320 * 80) return;
        int n = i / 80, k = i - n * 80;
        float w = lw[i];
        bf16 hi = __float2bfloat16_rn(w);
        bf16 lo = __float2bfloat16_rn(w - __bfloat162float(hi));
        bf16* dst = g_linw3 + (size_t)n * 256;
        dst[k] = hi;
        dst[80 + k] = hi;
        dst[160 + k] = lo;
        if (k < 16) dst[240 + k] = __float2bfloat16_rn(0.f);
        return;
    }
    const float* W;
    bf16* W3;
    int N, K;
    size_t stride;
    if      (seg == 0) { W = qw;  W3 = g_qkvw3;                      N = 320;  K = 320;  stride = (size_t)640 * 960; }
    else if (seg == 1) { W = kw;  W3 = g_qkvw3 + (size_t)320 * 960;  N = 160;  K = 320;  stride = (size_t)640 * 960; }
    else if (seg == 2) { W = vw;  W3 = g_qkvw3 + (size_t)480 * 960;  N = 160;  K = 320;  stride = (size_t)640 * 960; }
    else if (seg == 3) { W = ow;  W3 = g_ow3;                        N = 320;  K = 320;  stride = (size_t)320 * 960; }
    else if (seg == 4) { W = f1w; W3 = g_fc1w3;                      N = 1280; K = 320;  stride = (size_t)1280 * 960; }
    else               { W = f2w; W3 = g_fc2w3;                      N = 320;  K = 1280; stride = (size_t)320 * 3840; }
    int per = N * K;
    int i = blockIdx.x * 256 + threadIdx.x;
    if (i >= per * 6) return;
    int l = i / per, rem = i - l * per;
    int n = rem / K, k = rem - n * K;
    float w = W[i];
    bf16 hi = __float2bfloat16_rn(w);
    bf16 lo = __float2bfloat16_rn(w - __bfloat162float(hi));
    bf16* dst = W3 + (size_t)l * stride + (size_t)n * 3 * K;
    dst[k] = hi;
    dst[K + k] = hi;
    dst[2 * K + k] = lo;
}

// ---------------- conv weight split ----------------
__global__ void prep_conv_kernel(const float* __restrict__ W, bf16* __restrict__ Wp,
                                 int Co, int Ci)
{
    int i = blockIdx.x * 256 + threadIdx.x;
    if (i >= Co * Ci * 5) return;
    int o = i / (Ci * 5), rem = i - o * (Ci * 5);
    int ci = rem / 5, j = rem - ci * 5;
    float w = W[i];
    bf16 hi = __float2bfloat16_rn(w);
    bf16 lo = __float2bfloat16_rn(w - __bfloat162float(hi));
    int Ci3 = 3 * Ci;
    size_t d = ((size_t)o * 5 + j) * Ci3 + ci;
    Wp[d] = hi;
    Wp[d + Ci] = hi;
    Wp[d + 2 * Ci] = lo;
}

// ---------------- CMVN + asinh: one warp per frame -> packed [hi|lo|hi|0] ----------------
__global__ void __launch_bounds__(256) cmvn_kernel(const float* __restrict__ audio,
                                                   const float* __restrict__ log_k)
{
    int frame = (blockIdx.x * 256 + threadIdx.x) >> 5;
    int lane  = threadIdx.x & 31;
    if (frame >= NFRM) return;
    const float* src = audio + (size_t)frame * 80;
    float v0 = src[lane];
    float v1 = src[lane + 32];
    float v2 = (lane < 16) ? src[lane + 64] : 0.f;
    float s  = v0 + v1 + v2;
    float s2 = v0 * v0 + v1 * v1 + v2 * v2;
    #pragma unroll
    for (int off = 16; off; off >>= 1) {
        s  += __shfl_xor_sync(0xffffffffu, s,  off);
        s2 += __shfl_xor_sync(0xffffffffu, s2, off);
    }
    float m    = s * (1.f / 80.f);
    float var  = s2 * (1.f / 80.f) - m * m;
    float rinv = rsqrtf(var + 1e-6f);
    float ek   = expf(log_k[0]);
    size_t base = (size_t)frame * 256;
    float w0 = asinhf(ek * (v0 - m) * rinv);
    bf16 h0 = __float2bfloat16_rn(w0);
    bf16 l0 = __float2bfloat16_rn(w0 - __bfloat162float(h0));
    g_xnp[base + lane] = h0;
    g_xnp[base + 80 + lane] = l0;
    g_xnp[base + 160 + lane] = h0;
    float w1 = asinhf(ek * (v1 - m) * rinv);
    bf16 h1 = __float2bfloat16_rn(w1);
    bf16 l1 = __float2bfloat16_rn(w1 - __bfloat162float(h1));
    g_xnp[base + lane + 32] = h1;
    g_xnp[base + 112 + lane] = l1;
    g_xnp[base + 192 + lane] = h1;
    if (lane < 16) {
        float w2 = asinhf(ek * (v2 - m) * rinv);
        bf16 h2 = __float2bfloat16_rn(w2);
        bf16 l2 = __float2bfloat16_rn(w2 - __bfloat162float(h2));
        g_xnp[base + lane + 64] = h2;
        g_xnp[base + 144 + lane] = l2;
        g_xnp[base + 224 + lane] = h2;
        g_xnp[base + 240 + lane] = __float2bfloat16_rn(0.f);
    }
}

// ---------------- LayerNorm with packed bf16 split output [hi|lo|hi] ----------------
__global__ void ln_pack_kernel(const float* __restrict__ x, const float* __restrict__ w,
                               bf16* __restrict__ y3)
{
    int t = blockIdx.x;
    int c = threadIdx.x;
    float v = x[(size_t)t * HID + c];
    float s = v, s2 = v * v;
    #pragma unroll
    for (int off = 16; off; off >>= 1) {
        s  += __shfl_down_sync(0xffffffffu, s,  off);
        s2 += __shfl_down_sync(0xffffffffu, s2, off);
    }
    __shared__ float ss[10], ss2[10];
    __shared__ float mean_s, rstd_s;
    int wid = c >> 5, lane = c & 31;
    if (lane == 0) { ss[wid] = s; ss2[wid] = s2; }
    __syncthreads();
    if (c == 0) {
        float ts = 0.f, ts2 = 0.f;
        #pragma unroll
        for (int i = 0; i < 10; i++) { ts += ss[i]; ts2 += ss2[i]; }
        float mean = ts * (1.f / 320.f);
        float var  = ts2 * (1.f / 320.f) - mean * mean;
        mean_s = mean;
        rstd_s = rsqrtf(var + 1e-5f);
    }
    __syncthreads();
    float yv = (v - mean_s) * rstd_s * w[c];
    bf16 hi = __float2bfloat16_rn(yv);
    bf16 lo = __float2bfloat16_rn(yv - __bfloat162float(hi));
    size_t base = (size_t)t * 960;
    y3[base + c] = hi;
    y3[base + 320 + c] = lo;
    y3[base + 640 + c] = hi;
}

// ---------------- combine: out = p0 + p1 (elementwise, for QKV split-K) ----------------
__global__ void __launch_bounds__(256) combine2_kernel(const float* __restrict__ p,
                                                       float* __restrict__ out, int total)
{
    int i = (blockIdx.x * 256 + threadIdx.x) * 4;
    if (i >= total) return;
    float4 a = *(const float4*)(p + i);
    float4 b = *(const float4*)(p + total + i);
    float4 o;
    o.x = a.x + b.x; o.y = a.y + b.y; o.z = a.z + b.z; o.w = a.w + b.w;
    *(float4*)(out + i) = o;
}

// ---------------- combine split-K partials + residual, then LN (+pack or fp32 out) -----
template<int FINAL>
__global__ void __launch_bounds__(320) combine_ln_kernel(const float* __restrict__ part, int S,
                                                         const float* __restrict__ w,
                                                         float* __restrict__ x,
                                                         bf16* __restrict__ y3,
                                                         float* __restrict__ yout)
{
    int t = blockIdx.x;
    int c = threadIdx.x;
    float v = x[(size_t)t * HID + c];
    for (int s = 0; s < S; s++)
        v += part[(size_t)s * MTOK * HID + (size_t)t * HID + c];
    x[(size_t)t * HID + c] = v;

    float s1 = v, s2 = v * v;
    #pragma unroll
    for (int off = 16; off; off >>= 1) {
        s1 += __shfl_down_sync(0xffffffffu, s1, off);
        s2 += __shfl_down_sync(0xffffffffu, s2, off);
    }
    __shared__ float ss[10], ss2[10];
    __shared__ float mean_s, rstd_s;
    int wid = c >> 5, lane = c & 31;
    if (lane == 0) { ss[wid] = s1; ss2[wid] = s2; }
    __syncthreads();
    if (c == 0) {
        float ts = 0.f, ts2 = 0.f;
        #pragma unroll
        for (int i = 0; i < 10; i++) { ts += ss[i]; ts2 += ss2[i]; }
        float mean = ts * (1.f / 320.f);
        float var  = ts2 * (1.f / 320.f) - mean * mean;
        mean_s = mean;
        rstd_s = rsqrtf(var + 1e-5f);
    }
    __syncthreads();
    float yv = (v - mean_s) * rstd_s * w[c];
    if (FINAL) {
        yout[(size_t)t * HID + c] = yv;
    } else {
        bf16 hi = __float2bfloat16_rn(yv);
        bf16 lo = __float2bfloat16_rn(yv - __bfloat162float(hi));
        size_t base = (size_t)t * 960;
        y3[base + c] = hi;
        y3[base + 320 + c] = lo;
        y3[base + 640 + c] = hi;
    }
}

// ======================= wmma common =======================
#define LDA 40
#define ST_A 5120
#define ST_ELEMS 7680
#define SMEM_BYTES 46080

__device__ __forceinline__ void g_load(const bf16* A3, const bf16* B3,
                                       bf16* As, bf16* Bs,
                                       int tid, int m0, int n0, int K3, int k0)
{
    #pragma unroll
    for (int i = 0; i < 4; i++) {
        int id = tid + i * 128;
        int r = id >> 2, c = id & 3;
        __pipeline_memcpy_async(As + r * LDA + c * 8,
                                A3 + (size_t)(m0 + r) * K3 + k0 + c * 8, 16);
    }
    #pragma unroll
    for (int i = 0; i < 2; i++) {
        int id = tid + i * 128;
        int r = id >> 2, c = id & 3;
        __pipeline_memcpy_async(Bs + r * LDA + c * 8,
                                B3 + (size_t)(n0 + r) * K3 + k0 + c * 8, 16);
    }
    __pipeline_commit();
}

__device__ __forceinline__ void c_load(const bf16* Ap, const bf16* Wp,
                                       bf16* As, bf16* Bs,
                                       int tid, int inbase, int t0, int tap,
                                       int n0, int Ci3, int k0)
{
    #pragma unroll
    for (int i = 0; i < 4; i++) {
        int id = tid + i * 128;
        int r = id >> 2, c = id & 3;
        int tau = 2 * (t0 + r) - 4 + tap;
        bf16* adst = As + r * LDA + c * 8;
        if (tau >= 0) {
            __pipeline_memcpy_async(adst, Ap + (size_t)(inbase + tau) * Ci3 + k0 + c * 8, 16);
        } else {
            *(uint4*)adst = make_uint4(0u, 0u, 0u, 0u);
        }
    }
    #pragma unroll
    for (int i = 0; i < 2; i++) {
        int id = tid + i * 128;
        int r = id >> 2, c = id & 3;
        __pipeline_memcpy_async(Bs + r * LDA + c * 8,
                                Wp + ((size_t)(n0 + r) * 5 + tap) * Ci3 + k0 + c * 8, 16);
    }
    __pipeline_commit();
}

// ---------------- wmma GEMM, 128x64 tile (4 warps x 32x64), optional split-K --------
// SPLIT>1: blockIdx.z selects K-slice; writes fp32 partial to C + z*M*ldc (plain store).
template<int ACT, int BETA, int PACK, int SPLIT>
__global__ void __launch_bounds__(128) wmma_gemm_kernel(
    const bf16* __restrict__ A3, const bf16* __restrict__ B3,
    float* __restrict__ C, bf16* __restrict__ P,
    int M, int N, int K3, int ldc, int packK)
{
    __shared__ __align__(16) char smem_raw[SMEM_BYTES];
    float* Cs = (float*)smem_raw;

    int tid = threadIdx.x;
    int w = tid >> 5;
    int m0 = blockIdx.y * 128;
    int n0 = blockIdx.x * 64;
    int kLen = K3 / SPLIT;
    int zOff = (SPLIT > 1) ? blockIdx.z * kLen : 0;
    float* Cb = (SPLIT > 1) ? (C + (size_t)blockIdx.z * M * ldc) : C;

    wmma::fragment<wmma::accumulator, 16, 16, 16, float> cfrag[2][4];
    #pragma unroll
    for (int mi = 0; mi < 2; mi++)
        #pragma unroll
        for (int nj = 0; nj < 4; nj++)
            wmma::fill_fragment(cfrag[mi][nj], 0.f);

    int nk = kLen / 32;
    {
        bf16* As0 = (bf16*)smem_raw;
        g_load(A3, B3, As0, As0 + ST_A, tid, m0, n0, K3, zOff);
        bf16* As1 = (bf16*)smem_raw + ST_ELEMS;
        if (nk > 1) g_load(A3, B3, As1, As1 + ST_A, tid, m0, n0, K3, zOff + 32);
        else        __pipeline_commit();
    }
    int st = 0;
    for (int kt = 0; kt < nk; kt++) {
        __pipeline_wait_prior(1);
        __syncthreads();
        bf16* Asc = (bf16*)smem_raw + st * ST_ELEMS;
        bf16* Bsc = Asc + ST_A;
        #pragma unroll
        for (int kk = 0; kk < 32; kk += 16) {
            wmma::fragment<wmma::matrix_a, 16, 16, 16, bf16, wmma::row_major> afrag[2];
            wmma::fragment<wmma::matrix_b, 16, 16, 16, bf16, wmma::col_major> bfrag[4];
            #pragma unroll
            for (int mi = 0; mi < 2; mi++)
                wmma::load_matrix_sync(afrag[mi], Asc + (w * 32 + mi * 16) * LDA + kk, LDA);
            #pragma unroll
            for (int nj = 0; nj < 4; nj++)
                wmma::load_matrix_sync(bfrag[nj], Bsc + (nj * 16) * LDA + kk, LDA);
            #pragma unroll
            for (int mi = 0; mi < 2; mi++)
                #pragma unroll
                for (int nj = 0; nj < 4; nj++)
                    wmma::mma_sync(cfrag[mi][nj], afrag[mi], bfrag[nj], cfrag[mi][nj]);
        }
        if (kt + 2 < nk) {
            int ns = kt + 2 - ((kt + 2) / 3) * 3;
            bf16* Asn = (bf16*)smem_raw + ns * ST_ELEMS;
            g_load(A3, B3, Asn, Asn + ST_A, tid, m0, n0, K3, zOff + (kt + 2) * 32);
        } else {
            __pipeline_commit();
        }
        st++; if (st == 3) st = 0;
    }
    __syncthreads();

    #pragma unroll
    for (int mi = 0; mi < 2; mi++)
        #pragma unroll
        for (int nj = 0; nj < 4; nj++)
            wmma::store_matrix_sync(Cs + (w * 32 + mi * 16) * 64 + nj * 16,
                                    cfrag[mi][nj], 64, wmma::mem_row_major);
    __syncthreads();

    #pragma unroll
    for (int it = 0; it < 16; it++) {
        int idx = it * 512 + tid * 4;
        int m = idx >> 6, n = idx & 63;
        float4 v4 = *(float4*)(Cs + idx);
        float vv[4] = {v4.x, v4.y, v4.z, v4.w};
        if (SPLIT > 1) {
            float4 o4;
            o4.x = vv[0]; o4.y = vv[1]; o4.z = vv[2]; o4.w = vv[3];
            *(float4*)(Cb + (size_t)(m0 + m) * ldc + n0 + n) = o4;
            continue;
        }
        if (BETA) {
            float4 c4 = *(const float4*)(Cb + (size_t)(m0 + m) * ldc + n0 + n);
            vv[0] += c4.x; vv[1] += c4.y; vv[2] += c4.z; vv[3] += c4.w;
        }
        if (ACT) {
            #pragma unroll
            for (int j = 0; j < 4; j++) vv[j] = vv[j] / (1.f + __expf(-vv[j]));
        }
        if (PACK) {
            size_t base = (size_t)(m0 + m) * 3 * packK + n0 + n;
            #pragma unroll
            for (int j = 0; j < 4; j++) {
                bf16 hi = __float2bfloat16_rn(vv[j]);
                bf16 lo = __float2bfloat16_rn(vv[j] - __bfloat162float(hi));
                P[base + j] = hi;
                P[base + packK + j] = lo;
                P[base + 2 * packK + j] = hi;
            }
        } else {
            float4 o4;
            o4.x = vv[0]; o4.y = vv[1]; o4.z = vv[2]; o4.w = vv[3];
            *(float4*)(Cb + (size_t)(m0 + m) * ldc + n0 + n) = o4;
        }
    }
}

// ---------------- wmma conv, 128-row tile ----------------
template<int ACT, int PACK>
__global__ void __launch_bounds__(128) wmma_conv_kernel(
    const bf16* __restrict__ Ap, const bf16* __restrict__ Wp,
    const float* __restrict__ bias,
    float* __restrict__ Cout, bf16* __restrict__ P,
    int Tin, int Tout, int Ci3, int Co, int packK)
{
    __shared__ __align__(16) char smem_raw[SMEM_BYTES];
    float* Cs = (float*)smem_raw;

    int tid = threadIdx.x;
    int w = tid >> 5;
    int tpb = Tout / 128;
    int b  = blockIdx.y / tpb;
    int t0 = (blockIdx.y % tpb) * 128;
    int n0 = blockIdx.x * 64;
    int inbase = b * Tin;

    wmma::fragment<wmma::accumulator, 16, 16, 16, float> cfrag[2][4];
    #pragma unroll
    for (int mi = 0; mi < 2; mi++)
        #pragma unroll
        for (int nj = 0; nj < 4; nj++)
            wmma::fill_fragment(cfrag[mi][nj], 0.f);

    int cpt = Ci3 / 32;
    int niter = 5 * cpt;
    {
        bf16* As0 = (bf16*)smem_raw;
        c_load(Ap, Wp, As0, As0 + ST_A, tid, inbase, t0, 0, n0, Ci3, 0);
        bf16* As1 = (bf16*)smem_raw + ST_ELEMS;
        int tap1 = 1 / cpt, k01 = (1 % cpt) * 32;
        if (niter > 1) c_load(Ap, Wp, As1, As1 + ST_A, tid, inbase, t0, tap1, n0, Ci3, k01);
        else           __pipeline_commit();
    }
    int st = 0;
    for (int it = 0; it < niter; it++) {
        __pipeline_wait_prior(1);
        __syncthreads();
        bf16* Asc = (bf16*)smem_raw + st * ST_ELEMS;
        bf16* Bsc = Asc + ST_A;
        #pragma unroll
        for (int kk = 0; kk < 32; kk += 16) {
            wmma::fragment<wmma::matrix_a, 16, 16, 16, bf16, wmma::row_major> afrag[2];
            wmma::fragment<wmma::matrix_b, 16, 16, 16, bf16, wmma::col_major> bfrag[4];
            #pragma unroll
            for (int mi = 0; mi < 2; mi++)
                wmma::load_matrix_sync(afrag[mi], Asc + (w * 32 + mi * 16) * LDA + kk, LDA);
            #pragma unroll
            for (int nj = 0; nj < 4; nj++)
                wmma::load_matrix_sync(bfrag[nj], Bsc + (nj * 16) * LDA + kk, LDA);
            #pragma unroll
            for (int mi = 0; mi < 2; mi++)
                #pragma unroll
                for (int nj = 0; nj < 4; nj++)
                    wmma::mma_sync(cfrag[mi][nj], afrag[mi], bfrag[nj], cfrag[mi][nj]);
        }
        if (it + 2 < niter) {
            int nxt = it + 2;
            int ns = nxt - (nxt / 3) * 3;
            int tap = nxt / cpt;
            int k0  = (nxt - tap * cpt) * 32;
            bf16* Asn = (bf16*)smem_raw + ns * ST_ELEMS;
            c_load(Ap, Wp, Asn, Asn + ST_A, tid, inbase, t0, tap, n0, Ci3, k0);
        } else {
            __pipeline_commit();
        }
        st++; if (st == 3) st = 0;
    }
    __syncthreads();

    #pragma unroll
    for (int mi = 0; mi < 2; mi++)
        #pragma unroll
        for (int nj = 0; nj < 4; nj++)
            wmma::store_matrix_sync(Cs + (w * 32 + mi * 16) * 64 + nj * 16,
                                    cfrag[mi][nj], 64, wmma::mem_row_major);
    __syncthreads();

    #pragma unroll
    for (int it = 0; it < 16; it++) {
        int idx = it * 512 + tid * 4;
        int m = idx >> 6, n = idx & 63;
        int orow = b * Tout + t0 + m;
        float4 v4 = *(float4*)(Cs + idx);
        float vv[4] = {v4.x, v4.y, v4.z, v4.w};
        #pragma unroll
        for (int j = 0; j < 4; j++) vv[j] += bias[n0 + n + j];
        if (ACT) {
            #pragma unroll
            for (int j = 0; j < 4; j++) vv[j] = vv[j] / (1.f + __expf(-vv[j]));
        }
        if (PACK) {
            size_t base = (size_t)orow * 3 * packK + n0 + n;
            #pragma unroll
            for (int j = 0; j < 4; j++) {
                bf16 hi = __float2bfloat16_rn(vv[j]);
                bf16 lo = __float2bfloat16_rn(vv[j] - __bfloat162float(hi));
                P[base + j] = hi;
                P[base + packK + j] = lo;
                P[base + 2 * packK + j] = hi;
            }
        } else {
            float4 o4;
            o4.x = vv[0]; o4.y = vv[1]; o4.z = vv[2]; o4.w = vv[3];
            *(float4*)(Cout + (size_t)orow * Co + n0 + n) = o4;
        }
    }
}

// ---------------- attention: smem-tiled, block = 8 heads x 16 queries ----------------
__global__ void __launch_bounds__(128) attn_kernel(int rw)
{
    __shared__ float kv[36 * 320];
    int t0 = blockIdx.x * 16;
    int b  = blockIdx.y;
    int tid = threadIdx.x;

    for (int idx = tid; idx < 36 * 320; idx += 128) {
        int row = idx / 320, col = idx - (idx / 320) * 320;
        int k = t0 - 15 + row;
        float v = 0.f;
        if (k >= 0 && k < TE)
            v = g_qkv[((size_t)b * TE + k) * 640 + 320 + col];
        kv[idx] = v;
    }
    __syncthreads();

    int h  = tid >> 4;
    int qi = tid & 15;
    int tq = t0 + qi;
    int kvh = h >> 1;
    const float* qp = g_qkv + ((size_t)b * TE + tq) * 640 + h * HD;
    float qv[HD];
    #pragma unroll
    for (int d = 0; d < HD; d++) qv[d] = qp[d];

    int k0 = tq - 15; if (k0 < 0) k0 = 0;
    int k1 = tq + (rw > 0 ? rw - 1 : 0); if (k1 > TE - 1) k1 = TE - 1;
    float m = -1e30f, l = 0.f;
    float acc[HD];
    #pragma unroll
    for (int d = 0; d < HD; d++) acc[d] = 0.f;
    const float scale = 0.15811388300841897f;

    for (int k = k0; k <= k1; k++) {
        const float* kp = kv + (k - (t0 - 15)) * 320 + kvh * HD;
        float s = 0.f;
        #pragma unroll
        for (int d = 0; d < HD; d++) s += qv[d] * kp[d];
        s *= scale;
        float nm = fmaxf(m, s);
        float f  = __expf(m - nm);
        float p  = __expf(s - nm);
        m = nm;
        l = l * f + p;
        const float* vp = kp + 160;
        #pragma unroll
        for (int d = 0; d < HD; d++) acc[d] = acc[d] * f + p * vp[d];
    }
    float rl = 1.f / l;
    size_t base = ((size_t)b * TE + tq) * 960 + h * HD;
    #pragma unroll
    for (int d = 0; d < HD; d++) {
        float v = acc[d] * rl;
        bf16 hi = __float2bfloat16_rn(v);
        bf16 lo = __float2bfloat16_rn(v - __bfloat162float(hi));
        g_att3[base + d] = hi;
        g_att3[base + 320 + d] = lo;
        g_att3[base + 640 + d] = hi;
    }
}

// ---------------- launch ----------------
extern "C" void kernel_launch(void* const* d_in, const int* in_sizes, int n_in,
                              void* d_out, int out_size)
{
    const float* audio   = (const float*)d_in[0];
    const float* log_k   = (const float*)d_in[2];
    const float* lin_w   = (const float*)d_in[3];
    const float* conv1_w = (const float*)d_in[4];
    const float* conv1_b = (const float*)d_in[5];
    const float* conv2_w = (const float*)d_in[6];
    const float* conv2_b = (const float*)d_in[7];
    const float* ln1_w   = (const float*)d_in[8];
    const float* q_w     = (const float*)d_in[9];
    const float* k_w     = (const float*)d_in[10];
    const float* v_w     = (const float*)d_in[11];
    const float* o_w     = (const float*)d_in[12];
    const float* ln2_w   = (const float*)d_in[13];
    const float* fc1_w   = (const float*)d_in[14];
    const float* fc2_w   = (const float*)d_in[15];
    const float* fln_w   = (const float*)d_in[16];

    bf16 *pxnp, *px0p, *pc1p, *ph3, *patt3, *pffn3, *plinw3, *pqkvw3, *pow3, *pfc1w3, *pfc2w3, *pw1p, *pw2p;
    float *px, *pqkv, *ppart;
    cudaGetSymbolAddress((void**)&pxnp,   g_xnp);
    cudaGetSymbolAddress((void**)&px0p,   g_x0p);
    cudaGetSymbolAddress((void**)&pc1p,   g_c1p);
    cudaGetSymbolAddress((void**)&px,     g_x);
    cudaGetSymbolAddress((void**)&pqkv,   g_qkv);
    cudaGetSymbolAddress((void**)&ppart,  g_part);
    cudaGetSymbolAddress((void**)&ph3,    g_h3);
    cudaGetSymbolAddress((void**)&patt3,  g_att3);
    cudaGetSymbolAddress((void**)&pffn3,  g_ffn3);
    cudaGetSymbolAddress((void**)&plinw3, g_linw3);
    cudaGetSymbolAddress((void**)&pqkvw3, g_qkvw3);
    cudaGetSymbolAddress((void**)&pow3,   g_ow3);
    cudaGetSymbolAddress((void**)&pfc1w3, g_fc1w3);
    cudaGetSymbolAddress((void**)&pfc2w3, g_fc2w3);
    cudaGetSymbolAddress((void**)&pw1p,   g_w1p);
    cudaGetSymbolAddress((void**)&pw2p,   g_w2p);

    float* nullC = 0;
    bf16*  nullP = 0;

    prep_all_kernel<<<dim3(9600, 7), 256>>>(q_w, k_w, v_w, o_w, fc1_w, fc2_w, lin_w);
    prep_conv_kernel<<<(640 * 320 * 5 + 255) / 256, 256>>>(conv1_w, pw1p, 640, 320);
    prep_conv_kernel<<<(320 * 640 * 5 + 255) / 256, 256>>>(conv2_w, pw2p, 320, 640);
    cmvn_kernel<<<NFRM / 8, 256>>>(audio, log_k);
    wmma_gemm_kernel<1, 0, 1, 1><<<dim3(320 / 64, NFRM / 128), 128>>>(
        pxnp, plinw3, nullC, px0p, NFRM, 320, 256, 0, 320);
    wmma_conv_kernel<1, 1><<<dim3(640 / 64, (T1 / 128) * BB), 128>>>(
        px0p, pw1p, conv1_b, nullC, pc1p, TF, T1, 960, 640, 640);
    wmma_conv_kernel<0, 0><<<dim3(320 / 64, (TE / 128) * BB), 128>>>(
        pc1p, pw2p, conv2_b, px, nullP, T1, TE, 1920, 320, 0);

    const int M = MTOK;
    static const int rws[6] = {4, 4, 0, 0, 4, 4};
    // initial LN for layer 0
    ln_pack_kernel<<<M, HID>>>(px, ln1_w, ph3);
    for (int i = 0; i < 6; i++) {
        // QKV split-K x2: grid 640 blocks
        wmma_gemm_kernel<0, 0, 0, 2><<<dim3(640 / 64, M / 128, 2), 128>>>(
            ph3, pqkvw3 + (size_t)i * 640 * 960, ppart, nullP, M, 640, 960, 640, 0);
        combine2_kernel<<<(M * 640) / 1024, 256>>>(ppart, pqkv, M * 640);
        attn_kernel<<<dim3(TE / 16, BB), 128>>>(rws[i]);
        // O-proj split-K x3: grid 480 blocks
        wmma_gemm_kernel<0, 0, 0, 3><<<dim3(320 / 64, M / 128, 3), 128>>>(
            patt3, pow3 + (size_t)i * 320 * 960, ppart, nullP, M, 320, 960, 320, 0);
        // x += O; LN(ln2) -> h3
        combine_ln_kernel<0><<<M, HID>>>(ppart, 3, ln2_w + (size_t)i * HID, px, ph3, nullC);
        // FC1 direct (grid 640)
        wmma_gemm_kernel<1, 0, 1, 1><<<dim3(1280 / 64, M / 128), 128>>>(
            ph3, pfc1w3 + (size_t)i * 1280 * 960, nullC, pffn3, M, 1280, 960, 0, 1280);
        // FC2 split-K x4: grid 640 blocks
        wmma_gemm_kernel<0, 0, 0, 4><<<dim3(320 / 64, M / 128, 4), 128>>>(
            pffn3, pfc2w3 + (size_t)i * 320 * 3840, ppart, nullP, M, 320, 3840, 320, 0);
        // x += FC2; LN(next ln1 or final) -> h3 / d_out
        if (i < 5)
            combine_ln_kernel<0><<<M, HID>>>(ppart, 4, ln1_w + (size_t)(i + 1) * HID,
                                             px, ph3, nullC);
        else
            combine_ln_kernel<1><<<M, HID>>>(ppart, 4, fln_w, px, nullP, (float*)d_out);
    }
}

// round 12
// speedup vs baseline: 1.8957x; 1.7203x over previous
#include <cuda_runtime.h>
#include <cuda_bf16.h>
#include <cuda_fp16.h>
#include <cuda_pipeline.h>
#include <mma.h>
#include <math.h>

using namespace nvcuda;

#define BB 4
#define TF 4096
#define T1 2048
#define TE 1024
#define HID 320
#define NH 8
#define NKV 4
#define HD 40
#define FFN_D 1280
#define MTOK (BB * TE)
#define NFRM (BB * TF)

typedef __half fp16;

// ---------------- scratch (static device globals; no allocation) ----------------
__device__ fp16  g_xn  [NFRM * 96];             // CMVN+asinh out, cols 80..95 zero
__device__ fp16  g_x0  [NFRM * HID];            // frontend linear out (fp16)
__device__ fp16  g_c1  [BB * T1 * 640];         // conv1 out (silu, fp16)
__device__ float g_x   [MTOK * HID];            // residual stream fp32
__device__ float g_part[4 * MTOK * 640];        // split-K partials fp32
__device__ fp16  g_h   [MTOK * HID];            // LN out fp16
__device__ fp16  g_att [MTOK * HID];            // attention out fp16
__device__ fp16  g_ffn [MTOK * FFN_D];          // silu(fc1) fp16
__device__ fp16  g_linw[320 * 96];
__device__ fp16  g_qkvw[6 * 640 * 320];
__device__ fp16  g_ow  [6 * 320 * 320];
__device__ fp16  g_fc1w[6 * 1280 * 320];
__device__ fp16  g_fc2w[6 * 320 * 1280];
__device__ fp16  g_w1  [640 * 5 * 320];
__device__ fp16  g_w2  [320 * 5 * 640];

// ---------------- all GEMM weight converts in ONE launch ----------------
__global__ void prep_all_kernel(const float* __restrict__ qw, const float* __restrict__ kw,
                                const float* __restrict__ vw, const float* __restrict__ ow,
                                const float* __restrict__ f1w, const float* __restrict__ f2w,
                                const float* __restrict__ lw)
{
    int seg = blockIdx.y;
    int i = blockIdx.x * 256 + threadIdx.x;
    if (seg == 6) {
        // lin_w [320][80] -> g_linw [320][96] (pad zeros)
        if (i >= 320 * 96) return;
        int n = i / 96, k = i - n * 96;
        g_linw[i] = (k < 80) ? __float2half_rn(lw[n * 80 + k]) : __float2half_rn(0.f);
        return;
    }
    const float* W;
    fp16* W2;
    int per;
    size_t stride;
    if      (seg == 0) { W = qw;  W2 = g_qkvw;              per = 320 * 320;  stride = (size_t)640 * 320; }
    else if (seg == 1) { W = kw;  W2 = g_qkvw + 320 * 320;  per = 160 * 320;  stride = (size_t)640 * 320; }
    else if (seg == 2) { W = vw;  W2 = g_qkvw + 480 * 320;  per = 160 * 320;  stride = (size_t)640 * 320; }
    else if (seg == 3) { W = ow;  W2 = g_ow;                per = 320 * 320;  stride = (size_t)320 * 320; }
    else if (seg == 4) { W = f1w; W2 = g_fc1w;              per = 1280 * 320; stride = (size_t)1280 * 320; }
    else               { W = f2w; W2 = g_fc2w;              per = 320 * 1280; stride = (size_t)320 * 1280; }
    if (i >= per * 6) return;
    int l = i / per, rem = i - l * per;
    W2[(size_t)l * stride + rem] = __float2half_rn(W[i]);
}

// ---------------- conv weight convert: W[Co][Ci][5] -> Wp[Co][5][Ci] ----------------
__global__ void prep_conv_kernel(const float* __restrict__ W, fp16* __restrict__ Wp,
                                 int Co, int Ci)
{
    int i = blockIdx.x * 256 + threadIdx.x;
    if (i >= Co * Ci * 5) return;
    int o = i / (Ci * 5), rem = i - o * (Ci * 5);
    int ci = rem / 5, j = rem - ci * 5;
    Wp[((size_t)o * 5 + j) * Ci + ci] = __float2half_rn(W[i]);
}

// ---------------- CMVN + asinh: one warp per frame -> fp16 [80 | 16 zeros] ----------------
__global__ void __launch_bounds__(256) cmvn_kernel(const float* __restrict__ audio,
                                                   const float* __restrict__ log_k)
{
    int frame = (blockIdx.x * 256 + threadIdx.x) >> 5;
    int lane  = threadIdx.x & 31;
    if (frame >= NFRM) return;
    const float* src = audio + (size_t)frame * 80;
    float v0 = src[lane];
    float v1 = src[lane + 32];
    float v2 = (lane < 16) ? src[lane + 64] : 0.f;
    float s  = v0 + v1 + v2;
    float s2 = v0 * v0 + v1 * v1 + v2 * v2;
    #pragma unroll
    for (int off = 16; off; off >>= 1) {
        s  += __shfl_xor_sync(0xffffffffu, s,  off);
        s2 += __shfl_xor_sync(0xffffffffu, s2, off);
    }
    float m    = s * (1.f / 80.f);
    float var  = s2 * (1.f / 80.f) - m * m;
    float rinv = rsqrtf(var + 1e-6f);
    float ek   = expf(log_k[0]);
    size_t base = (size_t)frame * 96;
    g_xn[base + lane]      = __float2half_rn(asinhf(ek * (v0 - m) * rinv));
    g_xn[base + lane + 32] = __float2half_rn(asinhf(ek * (v1 - m) * rinv));
    if (lane < 16) {
        g_xn[base + lane + 64] = __float2half_rn(asinhf(ek * (v2 - m) * rinv));
        g_xn[base + lane + 80] = __float2half_rn(0.f);
    }
}

// ---------------- LayerNorm -> fp16 h ----------------
__global__ void __launch_bounds__(320) ln_h_kernel(const float* __restrict__ x,
                                                   const float* __restrict__ w,
                                                   fp16* __restrict__ y)
{
    int t = blockIdx.x;
    int c = threadIdx.x;
    float v = x[(size_t)t * HID + c];
    float s = v, s2 = v * v;
    #pragma unroll
    for (int off = 16; off; off >>= 1) {
        s  += __shfl_down_sync(0xffffffffu, s,  off);
        s2 += __shfl_down_sync(0xffffffffu, s2, off);
    }
    __shared__ float ss[10], ss2[10];
    __shared__ float mean_s, rstd_s;
    int wid = c >> 5, lane = c & 31;
    if (lane == 0) { ss[wid] = s; ss2[wid] = s2; }
    __syncthreads();
    if (c == 0) {
        float ts = 0.f, ts2 = 0.f;
        #pragma unroll
        for (int i = 0; i < 10; i++) { ts += ss[i]; ts2 += ss2[i]; }
        float mean = ts * (1.f / 320.f);
        float var  = ts2 * (1.f / 320.f) - mean * mean;
        mean_s = mean;
        rstd_s = rsqrtf(var + 1e-5f);
    }
    __syncthreads();
    y[(size_t)t * HID + c] = __float2half_rn((v - mean_s) * rstd_s * w[c]);
}

// ---------------- combine split-K partials + residual, then LN (fp16 h or fp32 out) -----
template<int FINAL>
__global__ void __launch_bounds__(320) combine_ln_kernel(const float* __restrict__ part, int S,
                                                         const float* __restrict__ w,
                                                         float* __restrict__ x,
                                                         fp16* __restrict__ y,
                                                         float* __restrict__ yout)
{
    int t = blockIdx.x;
    int c = threadIdx.x;
    float v = x[(size_t)t * HID + c];
    for (int s = 0; s < S; s++)
        v += part[(size_t)s * MTOK * HID + (size_t)t * HID + c];
    x[(size_t)t * HID + c] = v;

    float s1 = v, s2 = v * v;
    #pragma unroll
    for (int off = 16; off; off >>= 1) {
        s1 += __shfl_down_sync(0xffffffffu, s1, off);
        s2 += __shfl_down_sync(0xffffffffu, s2, off);
    }
    __shared__ float ss[10], ss2[10];
    __shared__ float mean_s, rstd_s;
    int wid = c >> 5, lane = c & 31;
    if (lane == 0) { ss[wid] = s1; ss2[wid] = s2; }
    __syncthreads();
    if (c == 0) {
        float ts = 0.f, ts2 = 0.f;
        #pragma unroll
        for (int i = 0; i < 10; i++) { ts += ss[i]; ts2 += ss2[i]; }
        float mean = ts * (1.f / 320.f);
        float var  = ts2 * (1.f / 320.f) - mean * mean;
        mean_s = mean;
        rstd_s = rsqrtf(var + 1e-5f);
    }
    __syncthreads();
    float yv = (v - mean_s) * rstd_s * w[c];
    if (FINAL) yout[(size_t)t * HID + c] = yv;
    else       y[(size_t)t * HID + c] = __float2half_rn(yv);
}

// ======================= wmma common =======================
#define LDA 40
#define ST_A 5120
#define ST_ELEMS 7680
#define SMEM_BYTES 46080

__device__ __forceinline__ void g_load(const fp16* A, const fp16* B,
                                       fp16* As, fp16* Bs,
                                       int tid, int m0, int n0, int K, int k0)
{
    #pragma unroll
    for (int i = 0; i < 4; i++) {
        int id = tid + i * 128;
        int r = id >> 2, c = id & 3;
        __pipeline_memcpy_async(As + r * LDA + c * 8,
                                A + (size_t)(m0 + r) * K + k0 + c * 8, 16);
    }
    #pragma unroll
    for (int i = 0; i < 2; i++) {
        int id = tid + i * 128;
        int r = id >> 2, c = id & 3;
        __pipeline_memcpy_async(Bs + r * LDA + c * 8,
                                B + (size_t)(n0 + r) * K + k0 + c * 8, 16);
    }
    __pipeline_commit();
}

__device__ __forceinline__ void c_load(const fp16* Ap, const fp16* Wp,
                                       fp16* As, fp16* Bs,
                                       int tid, int inbase, int t0, int tap,
                                       int n0, int Ci, int k0)
{
    #pragma unroll
    for (int i = 0; i < 4; i++) {
        int id = tid + i * 128;
        int r = id >> 2, c = id & 3;
        int tau = 2 * (t0 + r) - 4 + tap;
        fp16* adst = As + r * LDA + c * 8;
        if (tau >= 0) {
            __pipeline_memcpy_async(adst, Ap + (size_t)(inbase + tau) * Ci + k0 + c * 8, 16);
        } else {
            *(uint4*)adst = make_uint4(0u, 0u, 0u, 0u);
        }
    }
    #pragma unroll
    for (int i = 0; i < 2; i++) {
        int id = tid + i * 128;
        int r = id >> 2, c = id & 3;
        __pipeline_memcpy_async(Bs + r * LDA + c * 8,
                                Wp + ((size_t)(n0 + r) * 5 + tap) * Ci + k0 + c * 8, 16);
    }
    __pipeline_commit();
}

// ---------------- wmma GEMM, 128x64 tile (4 warps x 32x64), optional split-K --------
template<int ACT, int PACK, int SPLIT>
__global__ void __launch_bounds__(128) wmma_gemm_kernel(
    const fp16* __restrict__ A, const fp16* __restrict__ B,
    float* __restrict__ C, fp16* __restrict__ P,
    int M, int N, int K, int ldc, int ldp)
{
    __shared__ __align__(16) char smem_raw[SMEM_BYTES];
    float* Cs = (float*)smem_raw;

    int tid = threadIdx.x;
    int w = tid >> 5;
    int m0 = blockIdx.y * 128;
    int n0 = blockIdx.x * 64;
    int kLen = K / SPLIT;
    int zOff = (SPLIT > 1) ? blockIdx.z * kLen : 0;
    float* Cb = (SPLIT > 1) ? (C + (size_t)blockIdx.z * M * ldc) : C;

    wmma::fragment<wmma::accumulator, 16, 16, 16, float> cfrag[2][4];
    #pragma unroll
    for (int mi = 0; mi < 2; mi++)
        #pragma unroll
        for (int nj = 0; nj < 4; nj++)
            wmma::fill_fragment(cfrag[mi][nj], 0.f);

    int nk = kLen / 32;
    {
        fp16* As0 = (fp16*)smem_raw;
        g_load(A, B, As0, As0 + ST_A, tid, m0, n0, K, zOff);
        fp16* As1 = (fp16*)smem_raw + ST_ELEMS;
        if (nk > 1) g_load(A, B, As1, As1 + ST_A, tid, m0, n0, K, zOff + 32);
        else        __pipeline_commit();
    }
    int st = 0;
    for (int kt = 0; kt < nk; kt++) {
        __pipeline_wait_prior(1);
        __syncthreads();
        fp16* Asc = (fp16*)smem_raw + st * ST_ELEMS;
        fp16* Bsc = Asc + ST_A;
        #pragma unroll
        for (int kk = 0; kk < 32; kk += 16) {
            wmma::fragment<wmma::matrix_a, 16, 16, 16, fp16, wmma::row_major> afrag[2];
            wmma::fragment<wmma::matrix_b, 16, 16, 16, fp16, wmma::col_major> bfrag[4];
            #pragma unroll
            for (int mi = 0; mi < 2; mi++)
                wmma::load_matrix_sync(afrag[mi], Asc + (w * 32 + mi * 16) * LDA + kk, LDA);
            #pragma unroll
            for (int nj = 0; nj < 4; nj++)
                wmma::load_matrix_sync(bfrag[nj], Bsc + (nj * 16) * LDA + kk, LDA);
            #pragma unroll
            for (int mi = 0; mi < 2; mi++)
                #pragma unroll
                for (int nj = 0; nj < 4; nj++)
                    wmma::mma_sync(cfrag[mi][nj], afrag[mi], bfrag[nj], cfrag[mi][nj]);
        }
        if (kt + 2 < nk) {
            int ns = kt + 2 - ((kt + 2) / 3) * 3;
            fp16* Asn = (fp16*)smem_raw + ns * ST_ELEMS;
            g_load(A, B, Asn, Asn + ST_A, tid, m0, n0, K, zOff + (kt + 2) * 32);
        } else {
            __pipeline_commit();
        }
        st++; if (st == 3) st = 0;
    }
    __syncthreads();

    #pragma unroll
    for (int mi = 0; mi < 2; mi++)
        #pragma unroll
        for (int nj = 0; nj < 4; nj++)
            wmma::store_matrix_sync(Cs + (w * 32 + mi * 16) * 64 + nj * 16,
                                    cfrag[mi][nj], 64, wmma::mem_row_major);
    __syncthreads();

    #pragma unroll
    for (int it = 0; it < 16; it++) {
        int idx = it * 512 + tid * 4;
        int m = idx >> 6, n = idx & 63;
        float4 v4 = *(float4*)(Cs + idx);
        float vv[4] = {v4.x, v4.y, v4.z, v4.w};
        if (SPLIT > 1) {
            float4 o4;
            o4.x = vv[0]; o4.y = vv[1]; o4.z = vv[2]; o4.w = vv[3];
            *(float4*)(Cb + (size_t)(m0 + m) * ldc + n0 + n) = o4;
            continue;
        }
        if (ACT) {
            #pragma unroll
            for (int j = 0; j < 4; j++) vv[j] = vv[j] / (1.f + __expf(-vv[j]));
        }
        if (PACK) {
            size_t base = (size_t)(m0 + m) * ldp + n0 + n;
            #pragma unroll
            for (int j = 0; j < 4; j++) P[base + j] = __float2half_rn(vv[j]);
        } else {
            float4 o4;
            o4.x = vv[0]; o4.y = vv[1]; o4.z = vv[2]; o4.w = vv[3];
            *(float4*)(Cb + (size_t)(m0 + m) * ldc + n0 + n) = o4;
        }
    }
}

// ---------------- wmma conv, 128-row tile ----------------
template<int ACT, int PACK>
__global__ void __launch_bounds__(128) wmma_conv_kernel(
    const fp16* __restrict__ Ap, const fp16* __restrict__ Wp,
    const float* __restrict__ bias,
    float* __restrict__ Cout, fp16* __restrict__ P,
    int Tin, int Tout, int Ci, int Co)
{
    __shared__ __align__(16) char smem_raw[SMEM_BYTES];
    float* Cs = (float*)smem_raw;

    int tid = threadIdx.x;
    int w = tid >> 5;
    int tpb = Tout / 128;
    int b  = blockIdx.y / tpb;
    int t0 = (blockIdx.y % tpb) * 128;
    int n0 = blockIdx.x * 64;
    int inbase = b * Tin;

    wmma::fragment<wmma::accumulator, 16, 16, 16, float> cfrag[2][4];
    #pragma unroll
    for (int mi = 0; mi < 2; mi++)
        #pragma unroll
        for (int nj = 0; nj < 4; nj++)
            wmma::fill_fragment(cfrag[mi][nj], 0.f);

    int cpt = Ci / 32;
    int niter = 5 * cpt;
    {
        fp16* As0 = (fp16*)smem_raw;
        c_load(Ap, Wp, As0, As0 + ST_A, tid, inbase, t0, 0, n0, Ci, 0);
        fp16* As1 = (fp16*)smem_raw + ST_ELEMS;
        int tap1 = 1 / cpt, k01 = (1 % cpt) * 32;
        if (niter > 1) c_load(Ap, Wp, As1, As1 + ST_A, tid, inbase, t0, tap1, n0, Ci, k01);
        else           __pipeline_commit();
    }
    int st = 0;
    for (int it = 0; it < niter; it++) {
        __pipeline_wait_prior(1);
        __syncthreads();
        fp16* Asc = (fp16*)smem_raw + st * ST_ELEMS;
        fp16* Bsc = Asc + ST_A;
        #pragma unroll
        for (int kk = 0; kk < 32; kk += 16) {
            wmma::fragment<wmma::matrix_a, 16, 16, 16, fp16, wmma::row_major> afrag[2];
            wmma::fragment<wmma::matrix_b, 16, 16, 16, fp16, wmma::col_major> bfrag[4];
            #pragma unroll
            for (int mi = 0; mi < 2; mi++)
                wmma::load_matrix_sync(afrag[mi], Asc + (w * 32 + mi * 16) * LDA + kk, LDA);
            #pragma unroll
            for (int nj = 0; nj < 4; nj++)
                wmma::load_matrix_sync(bfrag[nj], Bsc + (nj * 16) * LDA + kk, LDA);
            #pragma unroll
            for (int mi = 0; mi < 2; mi++)
                #pragma unroll
                for (int nj = 0; nj < 4; nj++)
                    wmma::mma_sync(cfrag[mi][nj], afrag[mi], bfrag[nj], cfrag[mi][nj]);
        }
        if (it + 2 < niter) {
            int nxt = it + 2;
            int ns = nxt - (nxt / 3) * 3;
            int tap = nxt / cpt;
            int k0  = (nxt - tap * cpt) * 32;
            fp16* Asn = (fp16*)smem_raw + ns * ST_ELEMS;
            c_load(Ap, Wp, Asn, Asn + ST_A, tid, inbase, t0, tap, n0, Ci, k0);
        } else {
            __pipeline_commit();
        }
        st++; if (st == 3) st = 0;
    }
    __syncthreads();

    #pragma unroll
    for (int mi = 0; mi < 2; mi++)
        #pragma unroll
        for (int nj = 0; nj < 4; nj++)
            wmma::store_matrix_sync(Cs + (w * 32 + mi * 16) * 64 + nj * 16,
                                    cfrag[mi][nj], 64, wmma::mem_row_major);
    __syncthreads();

    #pragma unroll
    for (int it = 0; it < 16; it++) {
        int idx = it * 512 + tid * 4;
        int m = idx >> 6, n = idx & 63;
        int orow = b * Tout + t0 + m;
        float4 v4 = *(float4*)(Cs + idx);
        float vv[4] = {v4.x, v4.y, v4.z, v4.w};
        #pragma unroll
        for (int j = 0; j < 4; j++) vv[j] += bias[n0 + n + j];
        if (ACT) {
            #pragma unroll
            for (int j = 0; j < 4; j++) vv[j] = vv[j] / (1.f + __expf(-vv[j]));
        }
        if (PACK) {
            size_t base = (size_t)orow * Co + n0 + n;
            #pragma unroll
            for (int j = 0; j < 4; j++) P[base + j] = __float2half_rn(vv[j]);
        } else {
            float4 o4;
            o4.x = vv[0]; o4.y = vv[1]; o4.z = vv[2]; o4.w = vv[3];
            *(float4*)(Cout + (size_t)orow * Co + n0 + n) = o4;
        }
    }
}

// ---------------- attention: fused QKV split-K combine; smem K+V window ----------------
// QKV partials in g_part: slice s at offset s*MTOK*640; row layout [q(320)|k(160)|v(160)].
__global__ void __launch_bounds__(128) attn_kernel(int rw)
{
    __shared__ float kv[36 * 320];
    int t0 = blockIdx.x * 16;
    int b  = blockIdx.y;
    int tid = threadIdx.x;
    const float* p0 = g_part;
    const float* p1 = g_part + (size_t)MTOK * 640;

    for (int idx = tid; idx < 36 * 320; idx += 128) {
        int row = idx / 320, col = idx - (idx / 320) * 320;
        int k = t0 - 15 + row;
        float v = 0.f;
        if (k >= 0 && k < TE) {
            size_t off = ((size_t)b * TE + k) * 640 + 320 + col;
            v = p0[off] + p1[off];
        }
        kv[idx] = v;
    }
    __syncthreads();

    int h  = tid >> 4;
    int qi = tid & 15;
    int tq = t0 + qi;
    int kvh = h >> 1;
    size_t qoff = ((size_t)b * TE + tq) * 640 + h * HD;
    float qv[HD];
    #pragma unroll
    for (int d = 0; d < HD; d++) qv[d] = p0[qoff + d] + p1[qoff + d];

    int k0 = tq - 15; if (k0 < 0) k0 = 0;
    int k1 = tq + (rw > 0 ? rw - 1 : 0); if (k1 > TE - 1) k1 = TE - 1;
    float m = -1e30f, l = 0.f;
    float acc[HD];
    #pragma unroll
    for (int d = 0; d < HD; d++) acc[d] = 0.f;
    const float scale = 0.15811388300841897f;

    for (int k = k0; k <= k1; k++) {
        const float* kp = kv + (k - (t0 - 15)) * 320 + kvh * HD;
        float s = 0.f;
        #pragma unroll
        for (int d = 0; d < HD; d++) s += qv[d] * kp[d];
        s *= scale;
        float nm = fmaxf(m, s);
        float f  = __expf(m - nm);
        float p  = __expf(s - nm);
        m = nm;
        l = l * f + p;
        const float* vp = kp + 160;
        #pragma unroll
        for (int d = 0; d < HD; d++) acc[d] = acc[d] * f + p * vp[d];
    }
    float rl = 1.f / l;
    size_t base = ((size_t)b * TE + tq) * HID + h * HD;
    #pragma unroll
    for (int d = 0; d < HD; d++)
        g_att[base + d] = __float2half_rn(acc[d] * rl);
}

// ---------------- launch ----------------
extern "C" void kernel_launch(void* const* d_in, const int* in_sizes, int n_in,
                              void* d_out, int out_size)
{
    const float* audio   = (const float*)d_in[0];
    const float* log_k   = (const float*)d_in[2];
    const float* lin_w   = (const float*)d_in[3];
    const float* conv1_w = (const float*)d_in[4];
    const float* conv1_b = (const float*)d_in[5];
    const float* conv2_w = (const float*)d_in[6];
    const float* conv2_b = (const float*)d_in[7];
    const float* ln1_w   = (const float*)d_in[8];
    const float* q_w     = (const float*)d_in[9];
    const float* k_w     = (const float*)d_in[10];
    const float* v_w     = (const float*)d_in[11];
    const float* o_w     = (const float*)d_in[12];
    const float* ln2_w   = (const float*)d_in[13];
    const float* fc1_w   = (const float*)d_in[14];
    const float* fc2_w   = (const float*)d_in[15];
    const float* fln_w   = (const float*)d_in[16];

    fp16 *pxn, *px0, *pc1, *ph, *patt, *pffn, *plinw, *pqkvw, *pow_, *pfc1w, *pfc2w, *pw1, *pw2;
    float *px, *ppart;
    cudaGetSymbolAddress((void**)&pxn,   g_xn);
    cudaGetSymbolAddress((void**)&px0,   g_x0);
    cudaGetSymbolAddress((void**)&pc1,   g_c1);
    cudaGetSymbolAddress((void**)&px,    g_x);
    cudaGetSymbolAddress((void**)&ppart, g_part);
    cudaGetSymbolAddress((void**)&ph,    g_h);
    cudaGetSymbolAddress((void**)&patt,  g_att);
    cudaGetSymbolAddress((void**)&pffn,  g_ffn);
    cudaGetSymbolAddress((void**)&plinw, g_linw);
    cudaGetSymbolAddress((void**)&pqkvw, g_qkvw);
    cudaGetSymbolAddress((void**)&pow_,  g_ow);
    cudaGetSymbolAddress((void**)&pfc1w, g_fc1w);
    cudaGetSymbolAddress((void**)&pfc2w, g_fc2w);
    cudaGetSymbolAddress((void**)&pw1,   g_w1);
    cudaGetSymbolAddress((void**)&pw2,   g_w2);

    float* nullC = 0;
    fp16*  nullP = 0;

    prep_all_kernel<<<dim3(9600, 7), 256>>>(q_w, k_w, v_w, o_w, fc1_w, fc2_w, lin_w);
    prep_conv_kernel<<<(640 * 320 * 5 + 255) / 256, 256>>>(conv1_w, pw1, 640, 320);
    prep_conv_kernel<<<(320 * 640 * 5 + 255) / 256, 256>>>(conv2_w, pw2, 320, 640);
    cmvn_kernel<<<NFRM / 8, 256>>>(audio, log_k);
    // frontend linear + SiLU -> fp16 x0: [NFRM,320] = xn[NFRM,96] x linw[320,96]^T
    wmma_gemm_kernel<1, 1, 1><<<dim3(5, NFRM / 128), 128>>>(
        pxn, plinw, nullC, px0, NFRM, 320, 96, 0, 320);
    // conv1 (silu, fp16 out)
    wmma_conv_kernel<1, 1><<<dim3(10, (T1 / 128) * BB), 128>>>(
        px0, pw1, conv1_b, nullC, pc1, TF, T1, 320, 640);
    // conv2 (fp32 residual out)
    wmma_conv_kernel<0, 0><<<dim3(5, (TE / 128) * BB), 128>>>(
        pc1, pw2, conv2_b, px, nullP, T1, TE, 640, 320);

    const int M = MTOK;
    static const int rws[6] = {4, 4, 0, 0, 4, 4};
    ln_h_kernel<<<M, HID>>>(px, ln1_w, ph);
    for (int i = 0; i < 6; i++) {
        // QKV split-K x2 (K=320 -> 160 each): grid 640
        wmma_gemm_kernel<0, 0, 2><<<dim3(10, M / 128, 2), 128>>>(
            ph, pqkvw + (size_t)i * 640 * 320, ppart, nullP, M, 640, 320, 640, 0);
        attn_kernel<<<dim3(TE / 16, BB), 128>>>(rws[i]);
        // O-proj split-K x2 (K=320): grid 320
        wmma_gemm_kernel<0, 0, 2><<<dim3(5, M / 128, 2), 128>>>(
            patt, pow_ + (size_t)i * 320 * 320, ppart, nullP, M, 320, 320, 320, 0);
        combine_ln_kernel<0><<<M, HID>>>(ppart, 2, ln2_w + (size_t)i * HID, px, ph, nullC);
        // FC1 (silu, fp16): grid 640
        wmma_gemm_kernel<1, 1, 1><<<dim3(20, M / 128), 128>>>(
            ph, pfc1w + (size_t)i * 1280 * 320, nullC, pffn, M, 1280, 320, 0, 1280);
        // FC2 split-K x4 (K=1280 -> 320 each): grid 640
        wmma_gemm_kernel<0, 0, 4><<<dim3(5, M / 128, 4), 128>>>(
            pffn, pfc2w + (size_t)i * 320 * 1280, ppart, nullP, M, 320, 1280, 320, 0);
        if (i < 5)
            combine_ln_kernel<0><<<M, HID>>>(ppart, 4, ln1_w + (size_t)(i + 1) * HID,
                                             px, ph, nullC);
        else
            combine_ln_kernel<1><<<M, HID>>>(ppart, 4, fln_w, px, nullP, (float*)d_out);
    }
}

// round 13
// speedup vs baseline: 2.1355x; 1.1265x over previous
#include <cuda_runtime.h>
#include <cuda_bf16.h>
#include <cuda_fp16.h>
#include <cuda_pipeline.h>
#include <mma.h>
#include <math.h>

using namespace nvcuda;

#define BB 4
#define TF 4096
#define T1 2048
#define TE 1024
#define HID 320
#define NH 8
#define NKV 4
#define HD 40
#define FFN_D 1280
#define MTOK (BB * TE)
#define NFRM (BB * TF)

typedef __half fp16;

// ---------------- scratch (static device globals; no allocation) ----------------
__device__ fp16  g_xn  [NFRM * 96];
__device__ fp16  g_x0  [NFRM * HID];
__device__ fp16  g_c1  [BB * T1 * 640];
__device__ float g_x   [MTOK * HID];
__device__ float g_qkv [MTOK * 640];
__device__ float g_part[4 * MTOK * HID];
__device__ fp16  g_h   [MTOK * HID];
__device__ fp16  g_att [MTOK * HID];
__device__ fp16  g_ffn [MTOK * FFN_D];
__device__ fp16  g_linw[320 * 96];
__device__ fp16  g_qkvw[6 * 640 * 320];
__device__ fp16  g_ow  [6 * 320 * 320];
__device__ fp16  g_fc1w[6 * 1280 * 320];
__device__ fp16  g_fc2w[6 * 320 * 1280];
__device__ fp16  g_w1  [640 * 5 * 320];
__device__ fp16  g_w2  [320 * 5 * 640];

// ---------------- all GEMM weight converts in ONE launch ----------------
__global__ void prep_all_kernel(const float* __restrict__ qw, const float* __restrict__ kw,
                                const float* __restrict__ vw, const float* __restrict__ ow,
                                const float* __restrict__ f1w, const float* __restrict__ f2w,
                                const float* __restrict__ lw)
{
    int seg = blockIdx.y;
    int i = blockIdx.x * 256 + threadIdx.x;
    if (seg == 6) {
        if (i >= 320 * 96) return;
        int n = i / 96, k = i - n * 96;
        g_linw[i] = (k < 80) ? __float2half_rn(lw[n * 80 + k]) : __float2half_rn(0.f);
        return;
    }
    const float* W;
    fp16* W2;
    int per;
    size_t stride;
    if      (seg == 0) { W = qw;  W2 = g_qkvw;              per = 320 * 320;  stride = (size_t)640 * 320; }
    else if (seg == 1) { W = kw;  W2 = g_qkvw + 320 * 320;  per = 160 * 320;  stride = (size_t)640 * 320; }
    else if (seg == 2) { W = vw;  W2 = g_qkvw + 480 * 320;  per = 160 * 320;  stride = (size_t)640 * 320; }
    else if (seg == 3) { W = ow;  W2 = g_ow;                per = 320 * 320;  stride = (size_t)320 * 320; }
    else if (seg == 4) { W = f1w; W2 = g_fc1w;              per = 1280 * 320; stride = (size_t)1280 * 320; }
    else               { W = f2w; W2 = g_fc2w;              per = 320 * 1280; stride = (size_t)320 * 1280; }
    if (i >= per * 6) return;
    int l = i / per, rem = i - l * per;
    W2[(size_t)l * stride + rem] = __float2half_rn(W[i]);
}

// ---------------- conv weight convert: W[Co][Ci][5] -> Wp[Co][5][Ci] ----------------
__global__ void prep_conv_kernel(const float* __restrict__ W, fp16* __restrict__ Wp,
                                 int Co, int Ci)
{
    int i = blockIdx.x * 256 + threadIdx.x;
    if (i >= Co * Ci * 5) return;
    int o = i / (Ci * 5), rem = i - o * (Ci * 5);
    int ci = rem / 5, j = rem - ci * 5;
    Wp[((size_t)o * 5 + j) * Ci + ci] = __float2half_rn(W[i]);
}

// ---------------- CMVN + asinh: one warp per frame -> fp16 [80 | 16 zeros] ----------------
__global__ void __launch_bounds__(256) cmvn_kernel(const float* __restrict__ audio,
                                                   const float* __restrict__ log_k)
{
    int frame = (blockIdx.x * 256 + threadIdx.x) >> 5;
    int lane  = threadIdx.x & 31;
    if (frame >= NFRM) return;
    const float* src = audio + (size_t)frame * 80;
    float v0 = src[lane];
    float v1 = src[lane + 32];
    float v2 = (lane < 16) ? src[lane + 64] : 0.f;
    float s  = v0 + v1 + v2;
    float s2 = v0 * v0 + v1 * v1 + v2 * v2;
    #pragma unroll
    for (int off = 16; off; off >>= 1) {
        s  += __shfl_xor_sync(0xffffffffu, s,  off);
        s2 += __shfl_xor_sync(0xffffffffu, s2, off);
    }
    float m    = s * (1.f / 80.f);
    float var  = s2 * (1.f / 80.f) - m * m;
    float rinv = rsqrtf(var + 1e-6f);
    float ek   = expf(log_k[0]);
    size_t base = (size_t)frame * 96;
    g_xn[base + lane]      = __float2half_rn(asinhf(ek * (v0 - m) * rinv));
    g_xn[base + lane + 32] = __float2half_rn(asinhf(ek * (v1 - m) * rinv));
    if (lane < 16) {
        g_xn[base + lane + 64] = __float2half_rn(asinhf(ek * (v2 - m) * rinv));
        g_xn[base + lane + 80] = __float2half_rn(0.f);
    }
}

// ---------------- LayerNorm -> fp16 h ----------------
__global__ void __launch_bounds__(320) ln_h_kernel(const float* __restrict__ x,
                                                   const float* __restrict__ w,
                                                   fp16* __restrict__ y)
{
    int t = blockIdx.x;
    int c = threadIdx.x;
    float v = x[(size_t)t * HID + c];
    float s = v, s2 = v * v;
    #pragma unroll
    for (int off = 16; off; off >>= 1) {
        s  += __shfl_down_sync(0xffffffffu, s,  off);
        s2 += __shfl_down_sync(0xffffffffu, s2, off);
    }
    __shared__ float ss[10], ss2[10];
    __shared__ float mean_s, rstd_s;
    int wid = c >> 5, lane = c & 31;
    if (lane == 0) { ss[wid] = s; ss2[wid] = s2; }
    __syncthreads();
    if (c == 0) {
        float ts = 0.f, ts2 = 0.f;
        #pragma unroll
        for (int i = 0; i < 10; i++) { ts += ss[i]; ts2 += ss2[i]; }
        float mean = ts * (1.f / 320.f);
        float var  = ts2 * (1.f / 320.f) - mean * mean;
        mean_s = mean;
        rstd_s = rsqrtf(var + 1e-5f);
    }
    __syncthreads();
    y[(size_t)t * HID + c] = __float2half_rn((v - mean_s) * rstd_s * w[c]);
}

// ---------------- combine split-K partials + residual, then LN (fp16 h or fp32 out) -----
template<int FINAL>
__global__ void __launch_bounds__(320) combine_ln_kernel(const float* __restrict__ part, int S,
                                                         const float* __restrict__ w,
                                                         float* __restrict__ x,
                                                         fp16* __restrict__ y,
                                                         float* __restrict__ yout)
{
    int t = blockIdx.x;
    int c = threadIdx.x;
    float v = x[(size_t)t * HID + c];
    for (int s = 0; s < S; s++)
        v += part[(size_t)s * MTOK * HID + (size_t)t * HID + c];
    x[(size_t)t * HID + c] = v;

    float s1 = v, s2 = v * v;
    #pragma unroll
    for (int off = 16; off; off >>= 1) {
        s1 += __shfl_down_sync(0xffffffffu, s1, off);
        s2 += __shfl_down_sync(0xffffffffu, s2, off);
    }
    __shared__ float ss[10], ss2[10];
    __shared__ float mean_s, rstd_s;
    int wid = c >> 5, lane = c & 31;
    if (lane == 0) { ss[wid] = s1; ss2[wid] = s2; }
    __syncthreads();
    if (c == 0) {
        float ts = 0.f, ts2 = 0.f;
        #pragma unroll
        for (int i = 0; i < 10; i++) { ts += ss[i]; ts2 += ss2[i]; }
        float mean = ts * (1.f / 320.f);
        float var  = ts2 * (1.f / 320.f) - mean * mean;
        mean_s = mean;
        rstd_s = rsqrtf(var + 1e-5f);
    }
    __syncthreads();
    float yv = (v - mean_s) * rstd_s * w[c];
    if (FINAL) yout[(size_t)t * HID + c] = yv;
    else       y[(size_t)t * HID + c] = __float2half_rn(yv);
}

// ======================= wmma common =======================
#define LDA 40
#define ST_A 5120
#define ST_ELEMS 7680
#define SMEM_BYTES 46080

__device__ __forceinline__ void g_load(const fp16* A, const fp16* B,
                                       fp16* As, fp16* Bs,
                                       int tid, int m0, int n0, int K, int k0)
{
    #pragma unroll
    for (int i = 0; i < 4; i++) {
        int id = tid + i * 128;
        int r = id >> 2, c = id & 3;
        __pipeline_memcpy_async(As + r * LDA + c * 8,
                                A + (size_t)(m0 + r) * K + k0 + c * 8, 16);
    }
    #pragma unroll
    for (int i = 0; i < 2; i++) {
        int id = tid + i * 128;
        int r = id >> 2, c = id & 3;
        __pipeline_memcpy_async(Bs + r * LDA + c * 8,
                                B + (size_t)(n0 + r) * K + k0 + c * 8, 16);
    }
    __pipeline_commit();
}

__device__ __forceinline__ void c_load(const fp16* Ap, const fp16* Wp,
                                       fp16* As, fp16* Bs,
                                       int tid, int inbase, int t0, int tap,
                                       int n0, int Ci, int k0)
{
    #pragma unroll
    for (int i = 0; i < 4; i++) {
        int id = tid + i * 128;
        int r = id >> 2, c = id & 3;
        int tau = 2 * (t0 + r) - 4 + tap;
        fp16* adst = As + r * LDA + c * 8;
        if (tau >= 0) {
            __pipeline_memcpy_async(adst, Ap + (size_t)(inbase + tau) * Ci + k0 + c * 8, 16);
        } else {
            *(uint4*)adst = make_uint4(0u, 0u, 0u, 0u);
        }
    }
    #pragma unroll
    for (int i = 0; i < 2; i++) {
        int id = tid + i * 128;
        int r = id >> 2, c = id & 3;
        __pipeline_memcpy_async(Bs + r * LDA + c * 8,
                                Wp + ((size_t)(n0 + r) * 5 + tap) * Ci + k0 + c * 8, 16);
    }
    __pipeline_commit();
}

// ---------------- wmma GEMM, 128x64 tile (4 warps x 32x64), compile-time NK ----------
// SPLIT>1: blockIdx.z selects K-slice of length NK*32; writes fp32 partial.
template<int ACT, int PACK, int SPLIT, int NK>
__global__ void __launch_bounds__(128) wmma_gemm_kernel(
    const fp16* __restrict__ A, const fp16* __restrict__ B,
    float* __restrict__ C, fp16* __restrict__ P,
    int M, int N, int K, int ldc, int ldp)
{
    __shared__ __align__(16) char smem_raw[SMEM_BYTES];
    float* Cs = (float*)smem_raw;

    int tid = threadIdx.x;
    int w = tid >> 5;
    int m0 = blockIdx.y * 128;
    int n0 = blockIdx.x * 64;
    int zOff = (SPLIT > 1) ? blockIdx.z * (NK * 32) : 0;
    float* Cb = (SPLIT > 1) ? (C + (size_t)blockIdx.z * M * ldc) : C;

    wmma::fragment<wmma::accumulator, 16, 16, 16, float> cfrag[2][4];
    #pragma unroll
    for (int mi = 0; mi < 2; mi++)
        #pragma unroll
        for (int nj = 0; nj < 4; nj++)
            wmma::fill_fragment(cfrag[mi][nj], 0.f);

    {
        fp16* As0 = (fp16*)smem_raw;
        g_load(A, B, As0, As0 + ST_A, tid, m0, n0, K, zOff);
        fp16* As1 = (fp16*)smem_raw + ST_ELEMS;
        if (NK > 1) g_load(A, B, As1, As1 + ST_A, tid, m0, n0, K, zOff + 32);
        else        __pipeline_commit();
    }
    #pragma unroll
    for (int kt = 0; kt < NK; kt++) {
        const int st = kt % 3;
        __pipeline_wait_prior(1);
        __syncthreads();
        fp16* Asc = (fp16*)smem_raw + st * ST_ELEMS;
        fp16* Bsc = Asc + ST_A;
        #pragma unroll
        for (int kk = 0; kk < 32; kk += 16) {
            wmma::fragment<wmma::matrix_a, 16, 16, 16, fp16, wmma::row_major> afrag[2];
            wmma::fragment<wmma::matrix_b, 16, 16, 16, fp16, wmma::col_major> bfrag[4];
            #pragma unroll
            for (int mi = 0; mi < 2; mi++)
                wmma::load_matrix_sync(afrag[mi], Asc + (w * 32 + mi * 16) * LDA + kk, LDA);
            #pragma unroll
            for (int nj = 0; nj < 4; nj++)
                wmma::load_matrix_sync(bfrag[nj], Bsc + (nj * 16) * LDA + kk, LDA);
            #pragma unroll
            for (int mi = 0; mi < 2; mi++)
                #pragma unroll
                for (int nj = 0; nj < 4; nj++)
                    wmma::mma_sync(cfrag[mi][nj], afrag[mi], bfrag[nj], cfrag[mi][nj]);
        }
        if (kt + 2 < NK) {
            const int ns = (kt + 2) % 3;
            fp16* Asn = (fp16*)smem_raw + ns * ST_ELEMS;
            g_load(A, B, Asn, Asn + ST_A, tid, m0, n0, K, zOff + (kt + 2) * 32);
        } else {
            __pipeline_commit();
        }
    }
    __syncthreads();

    #pragma unroll
    for (int mi = 0; mi < 2; mi++)
        #pragma unroll
        for (int nj = 0; nj < 4; nj++)
            wmma::store_matrix_sync(Cs + (w * 32 + mi * 16) * 64 + nj * 16,
                                    cfrag[mi][nj], 64, wmma::mem_row_major);
    __syncthreads();

    #pragma unroll
    for (int it = 0; it < 16; it++) {
        int idx = it * 512 + tid * 4;
        int m = idx >> 6, n = idx & 63;
        float4 v4 = *(float4*)(Cs + idx);
        float vv[4] = {v4.x, v4.y, v4.z, v4.w};
        if (ACT) {
            #pragma unroll
            for (int j = 0; j < 4; j++) vv[j] = vv[j] / (1.f + __expf(-vv[j]));
        }
        if (PACK) {
            size_t base = (size_t)(m0 + m) * ldp + n0 + n;
            #pragma unroll
            for (int j = 0; j < 4; j++) P[base + j] = __float2half_rn(vv[j]);
        } else {
            float4 o4;
            o4.x = vv[0]; o4.y = vv[1]; o4.z = vv[2]; o4.w = vv[3];
            *(float4*)(Cb + (size_t)(m0 + m) * ldc + n0 + n) = o4;
        }
    }
}

// ---------------- wmma conv, 128-row tile ----------------
template<int ACT, int PACK>
__global__ void __launch_bounds__(128) wmma_conv_kernel(
    const fp16* __restrict__ Ap, const fp16* __restrict__ Wp,
    const float* __restrict__ bias,
    float* __restrict__ Cout, fp16* __restrict__ P,
    int Tin, int Tout, int Ci, int Co)
{
    __shared__ __align__(16) char smem_raw[SMEM_BYTES];
    float* Cs = (float*)smem_raw;

    int tid = threadIdx.x;
    int w = tid >> 5;
    int tpb = Tout / 128;
    int b  = blockIdx.y / tpb;
    int t0 = (blockIdx.y % tpb) * 128;
    int n0 = blockIdx.x * 64;
    int inbase = b * Tin;

    wmma::fragment<wmma::accumulator, 16, 16, 16, float> cfrag[2][4];
    #pragma unroll
    for (int mi = 0; mi < 2; mi++)
        #pragma unroll
        for (int nj = 0; nj < 4; nj++)
            wmma::fill_fragment(cfrag[mi][nj], 0.f);

    int cpt = Ci / 32;
    int niter = 5 * cpt;
    {
        fp16* As0 = (fp16*)smem_raw;
        c_load(Ap, Wp, As0, As0 + ST_A, tid, inbase, t0, 0, n0, Ci, 0);
        fp16* As1 = (fp16*)smem_raw + ST_ELEMS;
        int tap1 = 1 / cpt, k01 = (1 % cpt) * 32;
        if (niter > 1) c_load(Ap, Wp, As1, As1 + ST_A, tid, inbase, t0, tap1, n0, Ci, k01);
        else           __pipeline_commit();
    }
    int st = 0;
    for (int it = 0; it < niter; it++) {
        __pipeline_wait_prior(1);
        __syncthreads();
        fp16* Asc = (fp16*)smem_raw + st * ST_ELEMS;
        fp16* Bsc = Asc + ST_A;
        #pragma unroll
        for (int kk = 0; kk < 32; kk += 16) {
            wmma::fragment<wmma::matrix_a, 16, 16, 16, fp16, wmma::row_major> afrag[2];
            wmma::fragment<wmma::matrix_b, 16, 16, 16, fp16, wmma::col_major> bfrag[4];
            #pragma unroll
            for (int mi = 0; mi < 2; mi++)
                wmma::load_matrix_sync(afrag[mi], Asc + (w * 32 + mi * 16) * LDA + kk, LDA);
            #pragma unroll
            for (int nj = 0; nj < 4; nj++)
                wmma::load_matrix_sync(bfrag[nj], Bsc + (nj * 16) * LDA + kk, LDA);
            #pragma unroll
            for (int mi = 0; mi < 2; mi++)
                #pragma unroll
                for (int nj = 0; nj < 4; nj++)
                    wmma::mma_sync(cfrag[mi][nj], afrag[mi], bfrag[nj], cfrag[mi][nj]);
        }
        if (it + 2 < niter) {
            int nxt = it + 2;
            int ns = nxt - (nxt / 3) * 3;
            int tap = nxt / cpt;
            int k0  = (nxt - tap * cpt) * 32;
            fp16* Asn = (fp16*)smem_raw + ns * ST_ELEMS;
            c_load(Ap, Wp, Asn, Asn + ST_A, tid, inbase, t0, tap, n0, Ci, k0);
        } else {
            __pipeline_commit();
        }
        st++; if (st == 3) st = 0;
    }
    __syncthreads();

    #pragma unroll
    for (int mi = 0; mi < 2; mi++)
        #pragma unroll
        for (int nj = 0; nj < 4; nj++)
            wmma::store_matrix_sync(Cs + (w * 32 + mi * 16) * 64 + nj * 16,
                                    cfrag[mi][nj], 64, wmma::mem_row_major);
    __syncthreads();

    #pragma unroll
    for (int it = 0; it < 16; it++) {
        int idx = it * 512 + tid * 4;
        int m = idx >> 6, n = idx & 63;
        int orow = b * Tout + t0 + m;
        float4 v4 = *(float4*)(Cs + idx);
        float vv[4] = {v4.x, v4.y, v4.z, v4.w};
        #pragma unroll
        for (int j = 0; j < 4; j++) vv[j] += bias[n0 + n + j];
        if (ACT) {
            #pragma unroll
            for (int j = 0; j < 4; j++) vv[j] = vv[j] / (1.f + __expf(-vv[j]));
        }
        if (PACK) {
            size_t base = (size_t)orow * Co + n0 + n;
            #pragma unroll
            for (int j = 0; j < 4; j++) P[base + j] = __float2half_rn(vv[j]);
        } else {
            float4 o4;
            o4.x = vv[0]; o4.y = vv[1]; o4.z = vv[2]; o4.w = vv[3];
            *(float4*)(Cout + (size_t)orow * Co + n0 + n) = o4;
        }
    }
}

// ---------------- attention: smem K+V window; reads fp32 g_qkv directly ----------------
__global__ void __launch_bounds__(128) attn_kernel(int rw)
{
    __shared__ float kv[36 * 320];
    int t0 = blockIdx.x * 16;
    int b  = blockIdx.y;
    int tid = threadIdx.x;

    for (int idx = tid; idx < 36 * 320; idx += 128) {
        int row = idx / 320, col = idx - (idx / 320) * 320;
        int k = t0 - 15 + row;
        float v = 0.f;
        if (k >= 0 && k < TE)
            v = g_qkv[((size_t)b * TE + k) * 640 + 320 + col];
        kv[idx] = v;
    }
    __syncthreads();

    int h  = tid >> 4;
    int qi = tid & 15;
    int tq = t0 + qi;
    int kvh = h >> 1;
    const float* qp = g_qkv + ((size_t)b * TE + tq) * 640 + h * HD;
    float qv[HD];
    #pragma unroll
    for (int d = 0; d < HD; d++) qv[d] = qp[d];

    int k0 = tq - 15; if (k0 < 0) k0 = 0;
    int k1 = tq + (rw > 0 ? rw - 1 : 0); if (k1 > TE - 1) k1 = TE - 1;
    float m = -1e30f, l = 0.f;
    float acc[HD];
    #pragma unroll
    for (int d = 0; d < HD; d++) acc[d] = 0.f;
    const float scale = 0.15811388300841897f;

    for (int k = k0; k <= k1; k++) {
        const float* kp = kv + (k - (t0 - 15)) * 320 + kvh * HD;
        float s = 0.f;
        #pragma unroll
        for (int d = 0; d < HD; d++) s += qv[d] * kp[d];
        s *= scale;
        float nm = fmaxf(m, s);
        float f  = __expf(m - nm);
        float p  = __expf(s - nm);
        m = nm;
        l = l * f + p;
        const float* vp = kp + 160;
        #pragma unroll
        for (int d = 0; d < HD; d++) acc[d] = acc[d] * f + p * vp[d];
    }
    float rl = 1.f / l;
    size_t base = ((size_t)b * TE + tq) * HID + h * HD;
    #pragma unroll
    for (int d = 0; d < HD; d++)
        g_att[base + d] = __float2half_rn(acc[d] * rl);
}

// ---------------- launch ----------------
extern "C" void kernel_launch(void* const* d_in, const int* in_sizes, int n_in,
                              void* d_out, int out_size)
{
    const float* audio   = (const float*)d_in[0];
    const float* log_k   = (const float*)d_in[2];
    const float* lin_w   = (const float*)d_in[3];
    const float* conv1_w = (const float*)d_in[4];
    const float* conv1_b = (const float*)d_in[5];
    const float* conv2_w = (const float*)d_in[6];
    const float* conv2_b = (const float*)d_in[7];
    const float* ln1_w   = (const float*)d_in[8];
    const float* q_w     = (const float*)d_in[9];
    const float* k_w     = (const float*)d_in[10];
    const float* v_w     = (const float*)d_in[11];
    const float* o_w     = (const float*)d_in[12];
    const float* ln2_w   = (const float*)d_in[13];
    const float* fc1_w   = (const float*)d_in[14];
    const float* fc2_w   = (const float*)d_in[15];
    const float* fln_w   = (const float*)d_in[16];

    fp16 *pxn, *px0, *pc1, *ph, *patt, *pffn, *plinw, *pqkvw, *pow_, *pfc1w, *pfc2w, *pw1, *pw2;
    float *px, *pqkv, *ppart;
    cudaGetSymbolAddress((void**)&pxn,   g_xn);
    cudaGetSymbolAddress((void**)&px0,   g_x0);
    cudaGetSymbolAddress((void**)&pc1,   g_c1);
    cudaGetSymbolAddress((void**)&px,    g_x);
    cudaGetSymbolAddress((void**)&pqkv,  g_qkv);
    cudaGetSymbolAddress((void**)&ppart, g_part);
    cudaGetSymbolAddress((void**)&ph,    g_h);
    cudaGetSymbolAddress((void**)&patt,  g_att);
    cudaGetSymbolAddress((void**)&pffn,  g_ffn);
    cudaGetSymbolAddress((void**)&plinw, g_linw);
    cudaGetSymbolAddress((void**)&pqkvw, g_qkvw);
    cudaGetSymbolAddress((void**)&pow_,  g_ow);
    cudaGetSymbolAddress((void**)&pfc1w, g_fc1w);
    cudaGetSymbolAddress((void**)&pfc2w, g_fc2w);
    cudaGetSymbolAddress((void**)&pw1,   g_w1);
    cudaGetSymbolAddress((void**)&pw2,   g_w2);

    float* nullC = 0;
    fp16*  nullP = 0;

    // ordered so launch #4 (ncu's sample) is a wmma_gemm
    prep_all_kernel<<<dim3(9600, 7), 256>>>(q_w, k_w, v_w, o_w, fc1_w, fc2_w, lin_w);  // 1
    prep_conv_kernel<<<(640 * 320 * 5 + 255) / 256, 256>>>(conv1_w, pw1, 640, 320);    // 2
    cmvn_kernel<<<NFRM / 8, 256>>>(audio, log_k);                                      // 3
    wmma_gemm_kernel<1, 1, 1, 3><<<dim3(5, NFRM / 128), 128>>>(                        // 4
        pxn, plinw, nullC, px0, NFRM, 320, 96, 0, 320);
    prep_conv_kernel<<<(320 * 640 * 5 + 255) / 256, 256>>>(conv2_w, pw2, 320, 640);    // 5
    wmma_conv_kernel<1, 1><<<dim3(10, (T1 / 128) * BB), 128>>>(
        px0, pw1, conv1_b, nullC, pc1, TF, T1, 320, 640);
    wmma_conv_kernel<0, 0><<<dim3(5, (TE / 128) * BB), 128>>>(
        pc1, pw2, conv2_b, px, nullP, T1, TE, 640, 320);

    const int M = MTOK;
    static const int rws[6] = {4, 4, 0, 0, 4, 4};
    ln_h_kernel<<<M, HID>>>(px, ln1_w, ph);
    for (int i = 0; i < 6; i++) {
        // QKV direct (K=320, NK=10): grid 320
        wmma_gemm_kernel<0, 0, 1, 10><<<dim3(10, M / 128), 128>>>(
            ph, pqkvw + (size_t)i * 640 * 320, pqkv, nullP, M, 640, 320, 640, 0);
        attn_kernel<<<dim3(TE / 16, BB), 128>>>(rws[i]);
        // O-proj split-K x2 (NK=5): grid 320
        wmma_gemm_kernel<0, 0, 2, 5><<<dim3(5, M / 128, 2), 128>>>(
            patt, pow_ + (size_t)i * 320 * 320, ppart, nullP, M, 320, 320, 320, 0);
        combine_ln_kernel<0><<<M, HID>>>(ppart, 2, ln2_w + (size_t)i * HID, px, ph, nullC);
        // FC1 (silu, fp16, NK=10): grid 640
        wmma_gemm_kernel<1, 1, 1, 10><<<dim3(20, M / 128), 128>>>(
            ph, pfc1w + (size_t)i * 1280 * 320, nullC, pffn, M, 1280, 320, 0, 1280);
        // FC2 split-K x4 (NK=10): grid 640
        wmma_gemm_kernel<0, 0, 4, 10><<<dim3(5, M / 128, 4), 128>>>(
            pffn, pfc2w + (size_t)i * 320 * 1280, ppart, nullP, M, 320, 1280, 320, 0);
        if (i < 5)
            combine_ln_kernel<0><<<M, HID>>>(ppart, 4, ln1_w + (size_t)(i + 1) * HID,
                                             px, ph, nullC);
        else
            combine_ln_kernel<1><<<M, HID>>>(ppart, 4, fln_w, px, nullP, (float*)d_out);
    }
}

// round 14
// speedup vs baseline: 2.1943x; 1.0275x over previous
#include <cuda_runtime.h>
#include <cuda_bf16.h>
#include <cuda_fp16.h>
#include <cuda_pipeline.h>
#include <mma.h>
#include <math.h>

using namespace nvcuda;

#define BB 4
#define TF 4096
#define T1 2048
#define TE 1024
#define HID 320
#define NH 8
#define NKV 4
#define HD 40
#define FFN_D 1280
#define MTOK (BB * TE)
#define NFRM (BB * TF)

typedef __half fp16;

// ---------------- scratch (static device globals; no allocation) ----------------
__device__ fp16  g_xn  [NFRM * 96];
__device__ fp16  g_x0  [NFRM * HID];
__device__ fp16  g_c1  [BB * T1 * 640];
__device__ float g_x   [MTOK * HID];
__device__ float g_qkv [MTOK * 640];
__device__ float g_part[4 * MTOK * HID];
__device__ fp16  g_h   [MTOK * HID];
__device__ fp16  g_att [MTOK * HID];
__device__ fp16  g_ffn [MTOK * FFN_D];
__device__ fp16  g_linw[320 * 96];
__device__ fp16  g_qkvw[6 * 640 * 320];
__device__ fp16  g_ow  [6 * 320 * 320];
__device__ fp16  g_fc1w[6 * 1280 * 320];
__device__ fp16  g_fc2w[6 * 320 * 1280];
__device__ fp16  g_w1  [640 * 5 * 320];
__device__ fp16  g_w2  [320 * 5 * 640];

// ---------------- ALL weight converts in ONE launch (GEMM + conv + lin) ----------------
__global__ void prep_all_kernel(const float* __restrict__ qw, const float* __restrict__ kw,
                                const float* __restrict__ vw, const float* __restrict__ ow,
                                const float* __restrict__ f1w, const float* __restrict__ f2w,
                                const float* __restrict__ lw, const float* __restrict__ c1w,
                                const float* __restrict__ c2w)
{
    int seg = blockIdx.y;
    int i = blockIdx.x * 256 + threadIdx.x;
    if (seg == 6) {
        if (i >= 320 * 96) return;
        int n = i / 96, k = i - n * 96;
        g_linw[i] = (k < 80) ? __float2half_rn(lw[n * 80 + k]) : __float2half_rn(0.f);
        return;
    }
    if (seg == 7) {
        // conv1_w [640][320][5] -> g_w1 [640][5][320]
        if (i >= 640 * 320 * 5) return;
        int o = i / 1600, rem = i - o * 1600;
        int ci = rem / 5, j = rem - ci * 5;
        g_w1[((size_t)o * 5 + j) * 320 + ci] = __float2half_rn(c1w[i]);
        return;
    }
    if (seg == 8) {
        // conv2_w [320][640][5] -> g_w2 [320][5][640]
        if (i >= 320 * 640 * 5) return;
        int o = i / 3200, rem = i - o * 3200;
        int ci = rem / 5, j = rem - ci * 5;
        g_w2[((size_t)o * 5 + j) * 640 + ci] = __float2half_rn(c2w[i]);
        return;
    }
    const float* W;
    fp16* W2;
    int per;
    size_t stride;
    if      (seg == 0) { W = qw;  W2 = g_qkvw;              per = 320 * 320;  stride = (size_t)640 * 320; }
    else if (seg == 1) { W = kw;  W2 = g_qkvw + 320 * 320;  per = 160 * 320;  stride = (size_t)640 * 320; }
    else if (seg == 2) { W = vw;  W2 = g_qkvw + 480 * 320;  per = 160 * 320;  stride = (size_t)640 * 320; }
    else if (seg == 3) { W = ow;  W2 = g_ow;                per = 320 * 320;  stride = (size_t)320 * 320; }
    else if (seg == 4) { W = f1w; W2 = g_fc1w;              per = 1280 * 320; stride = (size_t)1280 * 320; }
    else               { W = f2w; W2 = g_fc2w;              per = 320 * 1280; stride = (size_t)320 * 1280; }
    if (i >= per * 6) return;
    int l = i / per, rem = i - l * per;
    W2[(size_t)l * stride + rem] = __float2half_rn(W[i]);
}

// ---------------- CMVN + asinh: one warp per frame -> fp16 [80 | 16 zeros] ----------------
__global__ void __launch_bounds__(256) cmvn_kernel(const float* __restrict__ audio,
                                                   const float* __restrict__ log_k)
{
    int frame = (blockIdx.x * 256 + threadIdx.x) >> 5;
    int lane  = threadIdx.x & 31;
    if (frame >= NFRM) return;
    const float* src = audio + (size_t)frame * 80;
    float v0 = src[lane];
    float v1 = src[lane + 32];
    float v2 = (lane < 16) ? src[lane + 64] : 0.f;
    float s  = v0 + v1 + v2;
    float s2 = v0 * v0 + v1 * v1 + v2 * v2;
    #pragma unroll
    for (int off = 16; off; off >>= 1) {
        s  += __shfl_xor_sync(0xffffffffu, s,  off);
        s2 += __shfl_xor_sync(0xffffffffu, s2, off);
    }
    float m    = s * (1.f / 80.f);
    float var  = s2 * (1.f / 80.f) - m * m;
    float rinv = rsqrtf(var + 1e-6f);
    float ek   = expf(log_k[0]);
    size_t base = (size_t)frame * 96;
    g_xn[base + lane]      = __float2half_rn(asinhf(ek * (v0 - m) * rinv));
    g_xn[base + lane + 32] = __float2half_rn(asinhf(ek * (v1 - m) * rinv));
    if (lane < 16) {
        g_xn[base + lane + 64] = __float2half_rn(asinhf(ek * (v2 - m) * rinv));
        g_xn[base + lane + 80] = __float2half_rn(0.f);
    }
}

// ---------------- LayerNorm -> fp16 h ----------------
__global__ void __launch_bounds__(320) ln_h_kernel(const float* __restrict__ x,
                                                   const float* __restrict__ w,
                                                   fp16* __restrict__ y)
{
    int t = blockIdx.x;
    int c = threadIdx.x;
    float v = x[(size_t)t * HID + c];
    float s = v, s2 = v * v;
    #pragma unroll
    for (int off = 16; off; off >>= 1) {
        s  += __shfl_down_sync(0xffffffffu, s,  off);
        s2 += __shfl_down_sync(0xffffffffu, s2, off);
    }
    __shared__ float ss[10], ss2[10];
    __shared__ float mean_s, rstd_s;
    int wid = c >> 5, lane = c & 31;
    if (lane == 0) { ss[wid] = s; ss2[wid] = s2; }
    __syncthreads();
    if (c == 0) {
        float ts = 0.f, ts2 = 0.f;
        #pragma unroll
        for (int i = 0; i < 10; i++) { ts += ss[i]; ts2 += ss2[i]; }
        float mean = ts * (1.f / 320.f);
        float var  = ts2 * (1.f / 320.f) - mean * mean;
        mean_s = mean;
        rstd_s = rsqrtf(var + 1e-5f);
    }
    __syncthreads();
    y[(size_t)t * HID + c] = __float2half_rn((v - mean_s) * rstd_s * w[c]);
}

// ---------------- combine split-K partials + residual, then LN (fp16 h or fp32 out) -----
template<int FINAL>
__global__ void __launch_bounds__(320) combine_ln_kernel(const float* __restrict__ part, int S,
                                                         const float* __restrict__ w,
                                                         float* __restrict__ x,
                                                         fp16* __restrict__ y,
                                                         float* __restrict__ yout)
{
    int t = blockIdx.x;
    int c = threadIdx.x;
    float v = x[(size_t)t * HID + c];
    for (int s = 0; s < S; s++)
        v += part[(size_t)s * MTOK * HID + (size_t)t * HID + c];
    x[(size_t)t * HID + c] = v;

    float s1 = v, s2 = v * v;
    #pragma unroll
    for (int off = 16; off; off >>= 1) {
        s1 += __shfl_down_sync(0xffffffffu, s1, off);
        s2 += __shfl_down_sync(0xffffffffu, s2, off);
    }
    __shared__ float ss[10], ss2[10];
    __shared__ float mean_s, rstd_s;
    int wid = c >> 5, lane = c & 31;
    if (lane == 0) { ss[wid] = s1; ss2[wid] = s2; }
    __syncthreads();
    if (c == 0) {
        float ts = 0.f, ts2 = 0.f;
        #pragma unroll
        for (int i = 0; i < 10; i++) { ts += ss[i]; ts2 += ss2[i]; }
        float mean = ts * (1.f / 320.f);
        float var  = ts2 * (1.f / 320.f) - mean * mean;
        mean_s = mean;
        rstd_s = rsqrtf(var + 1e-5f);
    }
    __syncthreads();
    float yv = (v - mean_s) * rstd_s * w[c];
    if (FINAL) yout[(size_t)t * HID + c] = yv;
    else       y[(size_t)t * HID + c] = __float2half_rn(yv);
}

// ======================= wmma common =======================
#define LDA 40
#define ST_A 5120
#define ST_ELEMS 7680
#define SMEM_BYTES 46080

__device__ __forceinline__ void g_load(const fp16* A, const fp16* B,
                                       fp16* As, fp16* Bs,
                                       int tid, int m0, int n0, int K, int k0)
{
    #pragma unroll
    for (int i = 0; i < 4; i++) {
        int id = tid + i * 128;
        int r = id >> 2, c = id & 3;
        __pipeline_memcpy_async(As + r * LDA + c * 8,
                                A + (size_t)(m0 + r) * K + k0 + c * 8, 16);
    }
    #pragma unroll
    for (int i = 0; i < 2; i++) {
        int id = tid + i * 128;
        int r = id >> 2, c = id & 3;
        __pipeline_memcpy_async(Bs + r * LDA + c * 8,
                                B + (size_t)(n0 + r) * K + k0 + c * 8, 16);
    }
    __pipeline_commit();
}

__device__ __forceinline__ void c_load(const fp16* Ap, const fp16* Wp,
                                       fp16* As, fp16* Bs,
                                       int tid, int inbase, int t0, int tap,
                                       int n0, int Ci, int k0)
{
    #pragma unroll
    for (int i = 0; i < 4; i++) {
        int id = tid + i * 128;
        int r = id >> 2, c = id & 3;
        int tau = 2 * (t0 + r) - 4 + tap;
        fp16* adst = As + r * LDA + c * 8;
        if (tau >= 0) {
            __pipeline_memcpy_async(adst, Ap + (size_t)(inbase + tau) * Ci + k0 + c * 8, 16);
        } else {
            *(uint4*)adst = make_uint4(0u, 0u, 0u, 0u);
        }
    }
    #pragma unroll
    for (int i = 0; i < 2; i++) {
        int id = tid + i * 128;
        int r = id >> 2, c = id & 3;
        __pipeline_memcpy_async(Bs + r * LDA + c * 8,
                                Wp + ((size_t)(n0 + r) * 5 + tap) * Ci + k0 + c * 8, 16);
    }
    __pipeline_commit();
}

// ---------------- wmma GEMM, 128x64 tile (4 warps x 32x64), compile-time NK ----------
// ACT==0 && PACK==0: fragments stored DIRECTLY to global (no smem epilogue, no barriers).
template<int ACT, int PACK, int SPLIT, int NK>
__global__ void __launch_bounds__(128) wmma_gemm_kernel(
    const fp16* __restrict__ A, const fp16* __restrict__ B,
    float* __restrict__ C, fp16* __restrict__ P,
    int M, int N, int K, int ldc, int ldp)
{
    __shared__ __align__(16) char smem_raw[SMEM_BYTES];
    float* Cs = (float*)smem_raw;

    int tid = threadIdx.x;
    int w = tid >> 5;
    int m0 = blockIdx.y * 128;
    int n0 = blockIdx.x * 64;
    int zOff = (SPLIT > 1) ? blockIdx.z * (NK * 32) : 0;
    float* Cb = (SPLIT > 1) ? (C + (size_t)blockIdx.z * M * ldc) : C;

    wmma::fragment<wmma::accumulator, 16, 16, 16, float> cfrag[2][4];
    #pragma unroll
    for (int mi = 0; mi < 2; mi++)
        #pragma unroll
        for (int nj = 0; nj < 4; nj++)
            wmma::fill_fragment(cfrag[mi][nj], 0.f);

    {
        fp16* As0 = (fp16*)smem_raw;
        g_load(A, B, As0, As0 + ST_A, tid, m0, n0, K, zOff);
        fp16* As1 = (fp16*)smem_raw + ST_ELEMS;
        if (NK > 1) g_load(A, B, As1, As1 + ST_A, tid, m0, n0, K, zOff + 32);
        else        __pipeline_commit();
    }
    #pragma unroll
    for (int kt = 0; kt < NK; kt++) {
        const int st = kt % 3;
        __pipeline_wait_prior(1);
        __syncthreads();
        fp16* Asc = (fp16*)smem_raw + st * ST_ELEMS;
        fp16* Bsc = Asc + ST_A;
        #pragma unroll
        for (int kk = 0; kk < 32; kk += 16) {
            wmma::fragment<wmma::matrix_a, 16, 16, 16, fp16, wmma::row_major> afrag[2];
            wmma::fragment<wmma::matrix_b, 16, 16, 16, fp16, wmma::col_major> bfrag[4];
            #pragma unroll
            for (int mi = 0; mi < 2; mi++)
                wmma::load_matrix_sync(afrag[mi], Asc + (w * 32 + mi * 16) * LDA + kk, LDA);
            #pragma unroll
            for (int nj = 0; nj < 4; nj++)
                wmma::load_matrix_sync(bfrag[nj], Bsc + (nj * 16) * LDA + kk, LDA);
            #pragma unroll
            for (int mi = 0; mi < 2; mi++)
                #pragma unroll
                for (int nj = 0; nj < 4; nj++)
                    wmma::mma_sync(cfrag[mi][nj], afrag[mi], bfrag[nj], cfrag[mi][nj]);
        }
        if (kt + 2 < NK) {
            const int ns = (kt + 2) % 3;
            fp16* Asn = (fp16*)smem_raw + ns * ST_ELEMS;
            g_load(A, B, Asn, Asn + ST_A, tid, m0, n0, K, zOff + (kt + 2) * 32);
        } else {
            __pipeline_commit();
        }
    }

    if (ACT == 0 && PACK == 0) {
        // direct global store: fp32 accum, bit-identical to smem path
        #pragma unroll
        for (int mi = 0; mi < 2; mi++)
            #pragma unroll
            for (int nj = 0; nj < 4; nj++)
                wmma::store_matrix_sync(Cb + (size_t)(m0 + w * 32 + mi * 16) * ldc
                                           + n0 + nj * 16,
                                        cfrag[mi][nj], ldc, wmma::mem_row_major);
        return;
    }

    __syncthreads();
    #pragma unroll
    for (int mi = 0; mi < 2; mi++)
        #pragma unroll
        for (int nj = 0; nj < 4; nj++)
            wmma::store_matrix_sync(Cs + (w * 32 + mi * 16) * 64 + nj * 16,
                                    cfrag[mi][nj], 64, wmma::mem_row_major);
    __syncthreads();

    #pragma unroll
    for (int it = 0; it < 16; it++) {
        int idx = it * 512 + tid * 4;
        int m = idx >> 6, n = idx & 63;
        float4 v4 = *(float4*)(Cs + idx);
        float vv[4] = {v4.x, v4.y, v4.z, v4.w};
        if (ACT) {
            #pragma unroll
            for (int j = 0; j < 4; j++) vv[j] = vv[j] / (1.f + __expf(-vv[j]));
        }
        if (PACK) {
            size_t base = (size_t)(m0 + m) * ldp + n0 + n;
            #pragma unroll
            for (int j = 0; j < 4; j++) P[base + j] = __float2half_rn(vv[j]);
        } else {
            float4 o4;
            o4.x = vv[0]; o4.y = vv[1]; o4.z = vv[2]; o4.w = vv[3];
            *(float4*)(Cb + (size_t)(m0 + m) * ldc + n0 + n) = o4;
        }
    }
}

// ---------------- wmma conv, 128-row tile ----------------
template<int ACT, int PACK>
__global__ void __launch_bounds__(128) wmma_conv_kernel(
    const fp16* __restrict__ Ap, const fp16* __restrict__ Wp,
    const float* __restrict__ bias,
    float* __restrict__ Cout, fp16* __restrict__ P,
    int Tin, int Tout, int Ci, int Co)
{
    __shared__ __align__(16) char smem_raw[SMEM_BYTES];
    float* Cs = (float*)smem_raw;

    int tid = threadIdx.x;
    int w = tid >> 5;
    int tpb = Tout / 128;
    int b  = blockIdx.y / tpb;
    int t0 = (blockIdx.y % tpb) * 128;
    int n0 = blockIdx.x * 64;
    int inbase = b * Tin;

    wmma::fragment<wmma::accumulator, 16, 16, 16, float> cfrag[2][4];
    #pragma unroll
    for (int mi = 0; mi < 2; mi++)
        #pragma unroll
        for (int nj = 0; nj < 4; nj++)
            wmma::fill_fragment(cfrag[mi][nj], 0.f);

    int cpt = Ci / 32;
    int niter = 5 * cpt;
    {
        fp16* As0 = (fp16*)smem_raw;
        c_load(Ap, Wp, As0, As0 + ST_A, tid, inbase, t0, 0, n0, Ci, 0);
        fp16* As1 = (fp16*)smem_raw + ST_ELEMS;
        int tap1 = 1 / cpt, k01 = (1 % cpt) * 32;
        if (niter > 1) c_load(Ap, Wp, As1, As1 + ST_A, tid, inbase, t0, tap1, n0, Ci, k01);
        else           __pipeline_commit();
    }
    int st = 0;
    for (int it = 0; it < niter; it++) {
        __pipeline_wait_prior(1);
        __syncthreads();
        fp16* Asc = (fp16*)smem_raw + st * ST_ELEMS;
        fp16* Bsc = Asc + ST_A;
        #pragma unroll
        for (int kk = 0; kk < 32; kk += 16) {
            wmma::fragment<wmma::matrix_a, 16, 16, 16, fp16, wmma::row_major> afrag[2];
            wmma::fragment<wmma::matrix_b, 16, 16, 16, fp16, wmma::col_major> bfrag[4];
            #pragma unroll
            for (int mi = 0; mi < 2; mi++)
                wmma::load_matrix_sync(afrag[mi], Asc + (w * 32 + mi * 16) * LDA + kk, LDA);
            #pragma unroll
            for (int nj = 0; nj < 4; nj++)
                wmma::load_matrix_sync(bfrag[nj], Bsc + (nj * 16) * LDA + kk, LDA);
            #pragma unroll
            for (int mi = 0; mi < 2; mi++)
                #pragma unroll
                for (int nj = 0; nj < 4; nj++)
                    wmma::mma_sync(cfrag[mi][nj], afrag[mi], bfrag[nj], cfrag[mi][nj]);
        }
        if (it + 2 < niter) {
            int nxt = it + 2;
            int ns = nxt - (nxt / 3) * 3;
            int tap = nxt / cpt;
            int k0  = (nxt - tap * cpt) * 32;
            fp16* Asn = (fp16*)smem_raw + ns * ST_ELEMS;
            c_load(Ap, Wp, Asn, Asn + ST_A, tid, inbase, t0, tap, n0, Ci, k0);
        } else {
            __pipeline_commit();
        }
        st++; if (st == 3) st = 0;
    }
    __syncthreads();

    #pragma unroll
    for (int mi = 0; mi < 2; mi++)
        #pragma unroll
        for (int nj = 0; nj < 4; nj++)
            wmma::store_matrix_sync(Cs + (w * 32 + mi * 16) * 64 + nj * 16,
                                    cfrag[mi][nj], 64, wmma::mem_row_major);
    __syncthreads();

    #pragma unroll
    for (int it = 0; it < 16; it++) {
        int idx = it * 512 + tid * 4;
        int m = idx >> 6, n = idx & 63;
        int orow = b * Tout + t0 + m;
        float4 v4 = *(float4*)(Cs + idx);
        float vv[4] = {v4.x, v4.y, v4.z, v4.w};
        #pragma unroll
        for (int j = 0; j < 4; j++) vv[j] += bias[n0 + n + j];
        if (ACT) {
            #pragma unroll
            for (int j = 0; j < 4; j++) vv[j] = vv[j] / (1.f + __expf(-vv[j]));
        }
        if (PACK) {
            size_t base = (size_t)orow * Co + n0 + n;
            #pragma unroll
            for (int j = 0; j < 4; j++) P[base + j] = __float2half_rn(vv[j]);
        } else {
            float4 o4;
            o4.x = vv[0]; o4.y = vv[1]; o4.z = vv[2]; o4.w = vv[3];
            *(float4*)(Cout + (size_t)orow * Co + n0 + n) = o4;
        }
    }
}

// ---------------- attention: smem K+V window; reads fp32 g_qkv directly ----------------
__global__ void __launch_bounds__(128) attn_kernel(int rw)
{
    __shared__ float kv[36 * 320];
    int t0 = blockIdx.x * 16;
    int b  = blockIdx.y;
    int tid = threadIdx.x;

    for (int idx = tid; idx < 36 * 320; idx += 128) {
        int row = idx / 320, col = idx - (idx / 320) * 320;
        int k = t0 - 15 + row;
        float v = 0.f;
        if (k >= 0 && k < TE)
            v = g_qkv[((size_t)b * TE + k) * 640 + 320 + col];
        kv[idx] = v;
    }
    __syncthreads();

    int h  = tid >> 4;
    int qi = tid & 15;
    int tq = t0 + qi;
    int kvh = h >> 1;
    const float* qp = g_qkv + ((size_t)b * TE + tq) * 640 + h * HD;
    float qv[HD];
    #pragma unroll
    for (int d = 0; d < HD; d++) qv[d] = qp[d];

    int k0 = tq - 15; if (k0 < 0) k0 = 0;
    int k1 = tq + (rw > 0 ? rw - 1 : 0); if (k1 > TE - 1) k1 = TE - 1;
    float m = -1e30f, l = 0.f;
    float acc[HD];
    #pragma unroll
    for (int d = 0; d < HD; d++) acc[d] = 0.f;
    const float scale = 0.15811388300841897f;

    for (int k = k0; k <= k1; k++) {
        const float* kp = kv + (k - (t0 - 15)) * 320 + kvh * HD;
        float s = 0.f;
        #pragma unroll
        for (int d = 0; d < HD; d++) s += qv[d] * kp[d];
        s *= scale;
        float nm = fmaxf(m, s);
        float f  = __expf(m - nm);
        float p  = __expf(s - nm);
        m = nm;
        l = l * f + p;
        const float* vp = kp + 160;
        #pragma unroll
        for (int d = 0; d < HD; d++) acc[d] = acc[d] * f + p * vp[d];
    }
    float rl = 1.f / l;
    size_t base = ((size_t)b * TE + tq) * HID + h * HD;
    #pragma unroll
    for (int d = 0; d < HD; d++)
        g_att[base + d] = __float2half_rn(acc[d] * rl);
}

// ---------------- launch ----------------
extern "C" void kernel_launch(void* const* d_in, const int* in_sizes, int n_in,
                              void* d_out, int out_size)
{
    const float* audio   = (const float*)d_in[0];
    const float* log_k   = (const float*)d_in[2];
    const float* lin_w   = (const float*)d_in[3];
    const float* conv1_w = (const float*)d_in[4];
    const float* conv1_b = (const float*)d_in[5];
    const float* conv2_w = (const float*)d_in[6];
    const float* conv2_b = (const float*)d_in[7];
    const float* ln1_w   = (const float*)d_in[8];
    const float* q_w     = (const float*)d_in[9];
    const float* k_w     = (const float*)d_in[10];
    const float* v_w     = (const float*)d_in[11];
    const float* o_w     = (const float*)d_in[12];
    const float* ln2_w   = (const float*)d_in[13];
    const float* fc1_w   = (const float*)d_in[14];
    const float* fc2_w   = (const float*)d_in[15];
    const float* fln_w   = (const float*)d_in[16];

    fp16 *pxn, *px0, *pc1, *ph, *patt, *pffn, *plinw, *pqkvw, *pow_, *pfc1w, *pfc2w, *pw1, *pw2;
    float *px, *pqkv, *ppart;
    cudaGetSymbolAddress((void**)&pxn,   g_xn);
    cudaGetSymbolAddress((void**)&px0,   g_x0);
    cudaGetSymbolAddress((void**)&pc1,   g_c1);
    cudaGetSymbolAddress((void**)&px,    g_x);
    cudaGetSymbolAddress((void**)&pqkv,  g_qkv);
    cudaGetSymbolAddress((void**)&ppart, g_part);
    cudaGetSymbolAddress((void**)&ph,    g_h);
    cudaGetSymbolAddress((void**)&patt,  g_att);
    cudaGetSymbolAddress((void**)&pffn,  g_ffn);
    cudaGetSymbolAddress((void**)&plinw, g_linw);
    cudaGetSymbolAddress((void**)&pqkvw, g_qkvw);
    cudaGetSymbolAddress((void**)&pow_,  g_ow);
    cudaGetSymbolAddress((void**)&pfc1w, g_fc1w);
    cudaGetSymbolAddress((void**)&pfc2w, g_fc2w);
    cudaGetSymbolAddress((void**)&pw1,   g_w1);
    cudaGetSymbolAddress((void**)&pw2,   g_w2);

    float* nullC = 0;
    fp16*  nullP = 0;

    // ordered so launch #4 (ncu's sample slot) is conv1
    prep_all_kernel<<<dim3(9600, 9), 256>>>(q_w, k_w, v_w, o_w, fc1_w, fc2_w,     // 1
                                            lin_w, conv1_w, conv2_w);
    cmvn_kernel<<<NFRM / 8, 256>>>(audio, log_k);                                  // 2
    wmma_gemm_kernel<1, 1, 1, 3><<<dim3(5, NFRM / 128), 128>>>(                    // 3
        pxn, plinw, nullC, px0, NFRM, 320, 96, 0, 320);
    wmma_conv_kernel<1, 1><<<dim3(10, (T1 / 128) * BB), 128>>>(                    // 4
        px0, pw1, conv1_b, nullC, pc1, TF, T1, 320, 640);
    wmma_conv_kernel<0, 0><<<dim3(5, (TE / 128) * BB), 128>>>(
        pc1, pw2, conv2_b, px, nullP, T1, TE, 640, 320);

    const int M = MTOK;
    static const int rws[6] = {4, 4, 0, 0, 4, 4};
    ln_h_kernel<<<M, HID>>>(px, ln1_w, ph);
    for (int i = 0; i < 6; i++) {
        // QKV direct (K=320, NK=10): grid 320, direct-global epilogue
        wmma_gemm_kernel<0, 0, 1, 10><<<dim3(10, M / 128), 128>>>(
            ph, pqkvw + (size_t)i * 640 * 320, pqkv, nullP, M, 640, 320, 640, 0);
        attn_kernel<<<dim3(TE / 16, BB), 128>>>(rws[i]);
        // O-proj split-K x2 (NK=5): grid 320, direct-global partials
        wmma_gemm_kernel<0, 0, 2, 5><<<dim3(5, M / 128, 2), 128>>>(
            patt, pow_ + (size_t)i * 320 * 320, ppart, nullP, M, 320, 320, 320, 0);
        combine_ln_kernel<0><<<M, HID>>>(ppart, 2, ln2_w + (size_t)i * HID, px, ph, nullC);
        // FC1 (silu, fp16, NK=10): grid 640, fused smem epilogue
        wmma_gemm_kernel<1, 1, 1, 10><<<dim3(20, M / 128), 128>>>(
            ph, pfc1w + (size_t)i * 1280 * 320, nullC, pffn, M, 1280, 320, 0, 1280);
        // FC2 split-K x4 (NK=10): grid 640, direct-global partials
        wmma_gemm_kernel<0, 0, 4, 10><<<dim3(5, M / 128, 4), 128>>>(
            pffn, pfc2w + (size_t)i * 320 * 1280, ppart, nullP, M, 320, 1280, 320, 0);
        if (i < 5)
            combine_ln_kernel<0><<<M, HID>>>(ppart, 4, ln1_w + (size_t)(i + 1) * HID,
                                             px, ph, nullC);
        else
            combine_ln_kernel<1><<<M, HID>>>(ppart, 4, fln_w, px, nullP, (float*)d_out);
    }
}

// round 17
// speedup vs baseline: 2.2942x; 1.0455x over previous
#include <cuda_runtime.h>
#include <cuda_bf16.h>
#include <cuda_fp16.h>
#include <cuda_pipeline.h>
#include <mma.h>
#include <math.h>

using namespace nvcuda;

#define BB 4
#define TF 4096
#define T1 2048
#define TE 1024
#define HID 320
#define NH 8
#define NKV 4
#define HD 40
#define FFN_D 1280
#define MTOK (BB * TE)
#define NFRM (BB * TF)

typedef __half fp16;

// ---------------- scratch (static device globals; no allocation) ----------------
__device__ fp16  g_xn  [NFRM * 96];
__device__ fp16  g_x0  [NFRM * HID];
__device__ fp16  g_c1  [BB * T1 * 640];
__device__ float g_x   [MTOK * HID];
__device__ float g_qkv [MTOK * 640];
__device__ float g_part[4 * MTOK * HID];
__device__ fp16  g_h   [MTOK * HID];
__device__ fp16  g_att [MTOK * HID];
__device__ fp16  g_ffn [MTOK * FFN_D];
__device__ fp16  g_linw[320 * 96];
__device__ fp16  g_qkvw[6 * 640 * 320];
__device__ fp16  g_ow  [6 * 320 * 320];
__device__ fp16  g_fc1w[6 * 1280 * 320];
__device__ fp16  g_fc2w[6 * 320 * 1280];
__device__ fp16  g_w1  [640 * 5 * 320];
__device__ fp16  g_w2  [320 * 5 * 640];

// ---------------- ALL prep (GEMM/conv/lin converts + CMVN) in ONE launch ----------------
__global__ void prep_all_kernel(const float* __restrict__ qw, const float* __restrict__ kw,
                                const float* __restrict__ vw, const float* __restrict__ ow,
                                const float* __restrict__ f1w, const float* __restrict__ f2w,
                                const float* __restrict__ lw, const float* __restrict__ c1w,
                                const float* __restrict__ c2w,
                                const float* __restrict__ audio,
                                const float* __restrict__ log_k)
{
    int seg = blockIdx.y;
    int i = blockIdx.x * 256 + threadIdx.x;
    if (seg == 9) {
        int frame = i >> 5;
        int lane  = threadIdx.x & 31;
        if (frame >= NFRM) return;
        const float* src = audio + (size_t)frame * 80;
        float v0 = src[lane];
        float v1 = src[lane + 32];
        float v2 = (lane < 16) ? src[lane + 64] : 0.f;
        float s  = v0 + v1 + v2;
        float s2 = v0 * v0 + v1 * v1 + v2 * v2;
        #pragma unroll
        for (int off = 16; off; off >>= 1) {
            s  += __shfl_xor_sync(0xffffffffu, s,  off);
            s2 += __shfl_xor_sync(0xffffffffu, s2, off);
        }
        float m    = s * (1.f / 80.f);
        float var  = s2 * (1.f / 80.f) - m * m;
        float rinv = rsqrtf(var + 1e-6f);
        float ek   = expf(log_k[0]);
        size_t base = (size_t)frame * 96;
        g_xn[base + lane]      = __float2half_rn(asinhf(ek * (v0 - m) * rinv));
        g_xn[base + lane + 32] = __float2half_rn(asinhf(ek * (v1 - m) * rinv));
        if (lane < 16) {
            g_xn[base + lane + 64] = __float2half_rn(asinhf(ek * (v2 - m) * rinv));
            g_xn[base + lane + 80] = __float2half_rn(0.f);
        }
        return;
    }
    if (seg == 6) {
        if (i >= 320 * 96) return;
        int n = i / 96, k = i - n * 96;
        g_linw[i] = (k < 80) ? __float2half_rn(lw[n * 80 + k]) : __float2half_rn(0.f);
        return;
    }
    if (seg == 7) {
        int e = i * 4;
        if (e >= 640 * 320 * 5) return;
        float4 v = *(const float4*)(c1w + e);
        float vv[4] = {v.x, v.y, v.z, v.w};
        #pragma unroll
        for (int j = 0; j < 4; j++) {
            int idx = e + j;
            int o = idx / 1600, rem = idx - o * 1600;
            int ci = rem / 5, t = rem - ci * 5;
            g_w1[((size_t)o * 5 + t) * 320 + ci] = __float2half_rn(vv[j]);
        }
        return;
    }
    if (seg == 8) {
        int e = i * 4;
        if (e >= 320 * 640 * 5) return;
        float4 v = *(const float4*)(c2w + e);
        float vv[4] = {v.x, v.y, v.z, v.w};
        #pragma unroll
        for (int j = 0; j < 4; j++) {
            int idx = e + j;
            int o = idx / 3200, rem = idx - o * 3200;
            int ci = rem / 5, t = rem - ci * 5;
            g_w2[((size_t)o * 5 + t) * 640 + ci] = __float2half_rn(vv[j]);
        }
        return;
    }
    const float* W;
    fp16* W2;
    int per;
    size_t stride;
    if      (seg == 0) { W = qw;  W2 = g_qkvw;              per = 320 * 320;  stride = (size_t)640 * 320; }
    else if (seg == 1) { W = kw;  W2 = g_qkvw + 320 * 320;  per = 160 * 320;  stride = (size_t)640 * 320; }
    else if (seg == 2) { W = vw;  W2 = g_qkvw + 480 * 320;  per = 160 * 320;  stride = (size_t)640 * 320; }
    else if (seg == 3) { W = ow;  W2 = g_ow;                per = 320 * 320;  stride = (size_t)320 * 320; }
    else if (seg == 4) { W = f1w; W2 = g_fc1w;              per = 1280 * 320; stride = (size_t)1280 * 320; }
    else               { W = f2w; W2 = g_fc2w;              per = 320 * 1280; stride = (size_t)320 * 1280; }
    int e = i * 4;
    if (e >= per * 6) return;
    float4 v = *(const float4*)(W + e);
    float vv[4] = {v.x, v.y, v.z, v.w};
    int l = e / per, rem = e - l * per;
    fp16* dst = W2 + (size_t)l * stride + rem;
    #pragma unroll
    for (int j = 0; j < 4; j++) dst[j] = __float2half_rn(vv[j]);
}

// ---------------- combine split-K partials + residual, then LN (fp16 h or fp32 out) -----
template<int FINAL>
__global__ void __launch_bounds__(320) combine_ln_kernel(const float* __restrict__ part, int S,
                                                         const float* __restrict__ w,
                                                         float* __restrict__ x,
                                                         fp16* __restrict__ y,
                                                         float* __restrict__ yout)
{
    int t = blockIdx.x;
    int c = threadIdx.x;
    float v = x[(size_t)t * HID + c];
    for (int s = 0; s < S; s++)
        v += part[(size_t)s * MTOK * HID + (size_t)t * HID + c];
    x[(size_t)t * HID + c] = v;

    float s1 = v, s2 = v * v;
    #pragma unroll
    for (int off = 16; off; off >>= 1) {
        s1 += __shfl_down_sync(0xffffffffu, s1, off);
        s2 += __shfl_down_sync(0xffffffffu, s2, off);
    }
    __shared__ float ss[10], ss2[10];
    __shared__ float mean_s, rstd_s;
    int wid = c >> 5, lane = c & 31;
    if (lane == 0) { ss[wid] = s1; ss2[wid] = s2; }
    __syncthreads();
    if (c == 0) {
        float ts = 0.f, ts2 = 0.f;
        #pragma unroll
        for (int i = 0; i < 10; i++) { ts += ss[i]; ts2 += ss2[i]; }
        float mean = ts * (1.f / 320.f);
        float var  = ts2 * (1.f / 320.f) - mean * mean;
        mean_s = mean;
        rstd_s = rsqrtf(var + 1e-5f);
    }
    __syncthreads();
    float yv = (v - mean_s) * rstd_s * w[c];
    if (FINAL) yout[(size_t)t * HID + c] = yv;
    else       y[(size_t)t * HID + c] = __float2half_rn(yv);
}

// ---------------- conv2 finisher: x = p0 + p1 + bias; LN -> fp16 h ----------------
__global__ void __launch_bounds__(320) combine_conv_ln_kernel(const float* __restrict__ part,
                                                              const float* __restrict__ bias,
                                                              const float* __restrict__ w,
                                                              float* __restrict__ x,
                                                              fp16* __restrict__ y)
{
    int t = blockIdx.x;
    int c = threadIdx.x;
    float v = part[(size_t)t * HID + c]
            + part[(size_t)MTOK * HID + (size_t)t * HID + c]
            + bias[c];
    x[(size_t)t * HID + c] = v;

    float s1 = v, s2 = v * v;
    #pragma unroll
    for (int off = 16; off; off >>= 1) {
        s1 += __shfl_down_sync(0xffffffffu, s1, off);
        s2 += __shfl_down_sync(0xffffffffu, s2, off);
    }
    __shared__ float ss[10], ss2[10];
    __shared__ float mean_s, rstd_s;
    int wid = c >> 5, lane = c & 31;
    if (lane == 0) { ss[wid] = s1; ss2[wid] = s2; }
    __syncthreads();
    if (c == 0) {
        float ts = 0.f, ts2 = 0.f;
        #pragma unroll
        for (int i = 0; i < 10; i++) { ts += ss[i]; ts2 += ss2[i]; }
        float mean = ts * (1.f / 320.f);
        float var  = ts2 * (1.f / 320.f) - mean * mean;
        mean_s = mean;
        rstd_s = rsqrtf(var + 1e-5f);
    }
    __syncthreads();
    y[(size_t)t * HID + c] = __float2half_rn((v - mean_s) * rstd_s * w[c]);
}

// ======================= wmma common =======================
#define LDA 40
#define ST_A 5120
#define ST_ELEMS 7680
#define SMEM_BYTES 46080

__device__ __forceinline__ void g_load(const fp16* A, const fp16* B,
                                       fp16* As, fp16* Bs,
                                       int tid, int m0, int n0, int K, int k0)
{
    #pragma unroll
    for (int i = 0; i < 4; i++) {
        int id = tid + i * 128;
        int r = id >> 2, c = id & 3;
        __pipeline_memcpy_async(As + r * LDA + c * 8,
                                A + (size_t)(m0 + r) * K + k0 + c * 8, 16);
    }
    #pragma unroll
    for (int i = 0; i < 2; i++) {
        int id = tid + i * 128;
        int r = id >> 2, c = id & 3;
        __pipeline_memcpy_async(Bs + r * LDA + c * 8,
                                B + (size_t)(n0 + r) * K + k0 + c * 8, 16);
    }
    __pipeline_commit();
}

__device__ __forceinline__ void c_load(const fp16* Ap, const fp16* Wp,
                                       fp16* As, fp16* Bs,
                                       int tid, int inbase, int t0, int tap,
                                       int n0, int Ci, int k0)
{
    #pragma unroll
    for (int i = 0; i < 4; i++) {
        int id = tid + i * 128;
        int r = id >> 2, c = id & 3;
        int tau = 2 * (t0 + r) - 4 + tap;
        fp16* adst = As + r * LDA + c * 8;
        if (tau >= 0) {
            __pipeline_memcpy_async(adst, Ap + (size_t)(inbase + tau) * Ci + k0 + c * 8, 16);
        } else {
            *(uint4*)adst = make_uint4(0u, 0u, 0u, 0u);
        }
    }
    #pragma unroll
    for (int i = 0; i < 2; i++) {
        int id = tid + i * 128;
        int r = id >> 2, c = id & 3;
        __pipeline_memcpy_async(Bs + r * LDA + c * 8,
                                Wp + ((size_t)(n0 + r) * 5 + tap) * Ci + k0 + c * 8, 16);
    }
    __pipeline_commit();
}

// ---------------- wmma GEMM, 128x64 tile (4 warps x 32x64), compile-time NK ----------
template<int ACT, int PACK, int SPLIT, int NK>
__global__ void __launch_bounds__(128) wmma_gemm_kernel(
    const fp16* __restrict__ A, const fp16* __restrict__ B,
    float* __restrict__ C, fp16* __restrict__ P,
    int M, int N, int K, int ldc, int ldp)
{
    __shared__ __align__(16) char smem_raw[SMEM_BYTES];
    float* Cs = (float*)smem_raw;

    int tid = threadIdx.x;
    int w = tid >> 5;
    int m0 = blockIdx.y * 128;
    int n0 = blockIdx.x * 64;
    int zOff = (SPLIT > 1) ? blockIdx.z * (NK * 32) : 0;
    float* Cb = (SPLIT > 1) ? (C + (size_t)blockIdx.z * M * ldc) : C;

    wmma::fragment<wmma::accumulator, 16, 16, 16, float> cfrag[2][4];
    #pragma unroll
    for (int mi = 0; mi < 2; mi++)
        #pragma unroll
        for (int nj = 0; nj < 4; nj++)
            wmma::fill_fragment(cfrag[mi][nj], 0.f);

    {
        fp16* As0 = (fp16*)smem_raw;
        g_load(A, B, As0, As0 + ST_A, tid, m0, n0, K, zOff);
        fp16* As1 = (fp16*)smem_raw + ST_ELEMS;
        if (NK > 1) g_load(A, B, As1, As1 + ST_A, tid, m0, n0, K, zOff + 32);
        else        __pipeline_commit();
    }
    #pragma unroll
    for (int kt = 0; kt < NK; kt++) {
        const int st = kt % 3;
        __pipeline_wait_prior(1);
        __syncthreads();
        fp16* Asc = (fp16*)smem_raw + st * ST_ELEMS;
        fp16* Bsc = Asc + ST_A;
        #pragma unroll
        for (int kk = 0; kk < 32; kk += 16) {
            wmma::fragment<wmma::matrix_a, 16, 16, 16, fp16, wmma::row_major> afrag[2];
            wmma::fragment<wmma::matrix_b, 16, 16, 16, fp16, wmma::col_major> bfrag[4];
            #pragma unroll
            for (int mi = 0; mi < 2; mi++)
                wmma::load_matrix_sync(afrag[mi], Asc + (w * 32 + mi * 16) * LDA + kk, LDA);
            #pragma unroll
            for (int nj = 0; nj < 4; nj++)
                wmma::load_matrix_sync(bfrag[nj], Bsc + (nj * 16) * LDA + kk, LDA);
            #pragma unroll
            for (int mi = 0; mi < 2; mi++)
                #pragma unroll
                for (int nj = 0; nj < 4; nj++)
                    wmma::mma_sync(cfrag[mi][nj], afrag[mi], bfrag[nj], cfrag[mi][nj]);
        }
        if (kt + 2 < NK) {
            const int ns = (kt + 2) % 3;
            fp16* Asn = (fp16*)smem_raw + ns * ST_ELEMS;
            g_load(A, B, Asn, Asn + ST_A, tid, m0, n0, K, zOff + (kt + 2) * 32);
        } else {
            __pipeline_commit();
        }
    }

    if (ACT == 0 && PACK == 0) {
        #pragma unroll
        for (int mi = 0; mi < 2; mi++)
            #pragma unroll
            for (int nj = 0; nj < 4; nj++)
                wmma::store_matrix_sync(Cb + (size_t)(m0 + w * 32 + mi * 16) * ldc
                                           + n0 + nj * 16,
                                        cfrag[mi][nj], ldc, wmma::mem_row_major);
        return;
    }

    __syncthreads();
    #pragma unroll
    for (int mi = 0; mi < 2; mi++)
        #pragma unroll
        for (int nj = 0; nj < 4; nj++)
            wmma::store_matrix_sync(Cs + (w * 32 + mi * 16) * 64 + nj * 16,
                                    cfrag[mi][nj], 64, wmma::mem_row_major);
    __syncthreads();

    #pragma unroll
    for (int it = 0; it < 16; it++) {
        int idx = it * 512 + tid * 4;
        int m = idx >> 6, n = idx & 63;
        float4 v4 = *(float4*)(Cs + idx);
        float vv[4] = {v4.x, v4.y, v4.z, v4.w};
        if (ACT) {
            #pragma unroll
            for (int j = 0; j < 4; j++) vv[j] = vv[j] / (1.f + __expf(-vv[j]));
        }
        if (PACK) {
            size_t base = (size_t)(m0 + m) * ldp + n0 + n;
            #pragma unroll
            for (int j = 0; j < 4; j++) P[base + j] = __float2half_rn(vv[j]);
        } else {
            float4 o4;
            o4.x = vv[0]; o4.y = vv[1]; o4.z = vv[2]; o4.w = vv[3];
            *(float4*)(Cb + (size_t)(m0 + m) * ldc + n0 + n) = o4;
        }
    }
}

// ---------------- wmma conv, 128-row tile, compile-time CI, optional Ci-split ----------
template<int ACT, int PACK, int CI, int SPLIT>
__global__ void __launch_bounds__(128) wmma_conv_kernel(
    const fp16* __restrict__ Ap, const fp16* __restrict__ Wp,
    const float* __restrict__ bias,
    float* __restrict__ Cout, fp16* __restrict__ P,
    int Tin, int Tout, int Co)
{
    __shared__ __align__(16) char smem_raw[SMEM_BYTES];
    float* Cs = (float*)smem_raw;

    const int CIS = CI / SPLIT;
    const int CPT = CIS / 32;
    const int NITER = 5 * CPT;

    int tid = threadIdx.x;
    int w = tid >> 5;
    int tpb = Tout / 128;
    int b  = blockIdx.y / tpb;
    int t0 = (blockIdx.y % tpb) * 128;
    int n0 = blockIdx.x * 64;
    int inbase = b * Tin;
    int zbase = (SPLIT > 1) ? blockIdx.z * CIS : 0;
    float* Cb = (SPLIT > 1) ? (Cout + (size_t)blockIdx.z * MTOK * HID) : Cout;

    wmma::fragment<wmma::accumulator, 16, 16, 16, float> cfrag[2][4];
    #pragma unroll
    for (int mi = 0; mi < 2; mi++)
        #pragma unroll
        for (int nj = 0; nj < 4; nj++)
            wmma::fill_fragment(cfrag[mi][nj], 0.f);

    {
        fp16* As0 = (fp16*)smem_raw;
        c_load(Ap, Wp, As0, As0 + ST_A, tid, inbase, t0, 0, n0, CI, zbase);
        fp16* As1 = (fp16*)smem_raw + ST_ELEMS;
        c_load(Ap, Wp, As1, As1 + ST_A, tid, inbase, t0, 1 / CPT, n0, CI,
               zbase + (1 % CPT) * 32);
    }
    int st = 0;
    for (int it = 0; it < NITER; it++) {
        __pipeline_wait_prior(1);
        __syncthreads();
        fp16* Asc = (fp16*)smem_raw + st * ST_ELEMS;
        fp16* Bsc = Asc + ST_A;
        #pragma unroll
        for (int kk = 0; kk < 32; kk += 16) {
            wmma::fragment<wmma::matrix_a, 16, 16, 16, fp16, wmma::row_major> afrag[2];
            wmma::fragment<wmma::matrix_b, 16, 16, 16, fp16, wmma::col_major> bfrag[4];
            #pragma unroll
            for (int mi = 0; mi < 2; mi++)
                wmma::load_matrix_sync(afrag[mi], Asc + (w * 32 + mi * 16) * LDA + kk, LDA);
            #pragma unroll
            for (int nj = 0; nj < 4; nj++)
                wmma::load_matrix_sync(bfrag[nj], Bsc + (nj * 16) * LDA + kk, LDA);
            #pragma unroll
            for (int mi = 0; mi < 2; mi++)
                #pragma unroll
                for (int nj = 0; nj < 4; nj++)
                    wmma::mma_sync(cfrag[mi][nj], afrag[mi], bfrag[nj], cfrag[mi][nj]);
        }
        if (it + 2 < NITER) {
            int nxt = it + 2;
            int ns = nxt % 3;
            int tap = nxt / CPT;
            int k0  = zbase + (nxt - tap * CPT) * 32;
            fp16* Asn = (fp16*)smem_raw + ns * ST_ELEMS;
            c_load(Ap, Wp, Asn, Asn + ST_A, tid, inbase, t0, tap, n0, CI, k0);
        } else {
            __pipeline_commit();
        }
        st++; if (st == 3) st = 0;
    }

    if (SPLIT > 1) {
        #pragma unroll
        for (int mi = 0; mi < 2; mi++)
            #pragma unroll
            for (int nj = 0; nj < 4; nj++)
                wmma::store_matrix_sync(Cb + (size_t)(b * Tout + t0 + w * 32 + mi * 16) * Co
                                           + n0 + nj * 16,
                                        cfrag[mi][nj], Co, wmma::mem_row_major);
        return;
    }

    __syncthreads();
    #pragma unroll
    for (int mi = 0; mi < 2; mi++)
        #pragma unroll
        for (int nj = 0; nj < 4; nj++)
            wmma::store_matrix_sync(Cs + (w * 32 + mi * 16) * 64 + nj * 16,
                                    cfrag[mi][nj], 64, wmma::mem_row_major);
    __syncthreads();

    #pragma unroll
    for (int it = 0; it < 16; it++) {
        int idx = it * 512 + tid * 4;
        int m = idx >> 6, n = idx & 63;
        int orow = b * Tout + t0 + m;
        float4 v4 = *(float4*)(Cs + idx);
        float vv[4] = {v4.x, v4.y, v4.z, v4.w};
        #pragma unroll
        for (int j = 0; j < 4; j++) vv[j] += bias[n0 + n + j];
        if (ACT) {
            #pragma unroll
            for (int j = 0; j < 4; j++) vv[j] = vv[j] / (1.f + __expf(-vv[j]));
        }
        if (PACK) {
            size_t base = (size_t)orow * Co + n0 + n;
            #pragma unroll
            for (int j = 0; j < 4; j++) P[base + j] = __float2half_rn(vv[j]);
        } else {
            float4 o4;
            o4.x = vv[0]; o4.y = vv[1]; o4.z = vv[2]; o4.w = vv[3];
            *(float4*)(Cout + (size_t)orow * Co + n0 + n) = o4;
        }
    }
}

// ---------------- attention: smem K+V window; reads fp32 g_qkv ----------------
__global__ void __launch_bounds__(128) attn_kernel(int rw)
{
    __shared__ float kv[36 * 320];
    int t0 = blockIdx.x * 16;
    int b  = blockIdx.y;
    int tid = threadIdx.x;

    for (int idx = tid; idx < 36 * 320; idx += 128) {
        int row = idx / 320, col = idx - (idx / 320) * 320;
        int k = t0 - 15 + row;
        float v = 0.f;
        if (k >= 0 && k < TE)
            v = g_qkv[((size_t)b * TE + k) * 640 + 320 + col];
        kv[idx] = v;
    }
    __syncthreads();

    int h  = tid >> 4;
    int qi = tid & 15;
    int tq = t0 + qi;
    int kvh = h >> 1;
    const float* qp = g_qkv + ((size_t)b * TE + tq) * 640 + h * HD;
    float qv[HD];
    #pragma unroll
    for (int d = 0; d < HD; d++) qv[d] = qp[d];

    int k0 = tq - 15; if (k0 < 0) k0 = 0;
    int k1 = tq + (rw > 0 ? rw - 1 : 0); if (k1 > TE - 1) k1 = TE - 1;
    float m = -1e30f, l = 0.f;
    float acc[HD];
    #pragma unroll
    for (int d = 0; d < HD; d++) acc[d] = 0.f;
    const float scale = 0.15811388300841897f;

    for (int k = k0; k <= k1; k++) {
        const float* kp = kv + (k - (t0 - 15)) * 320 + kvh * HD;
        float s = 0.f;
        #pragma unroll
        for (int d = 0; d < HD; d++) s += qv[d] * kp[d];
        s *= scale;
        float nm = fmaxf(m, s);
        float f  = __expf(m - nm);
        float p  = __expf(s - nm);
        m = nm;
        l = l * f + p;
        const float* vp = kp + 160;
        #pragma unroll
        for (int d = 0; d < HD; d++) acc[d] = acc[d] * f + p * vp[d];
    }
    float rl = 1.f / l;
    size_t base = ((size_t)b * TE + tq) * HID + h * HD;
    #pragma unroll
    for (int d = 0; d < HD; d++)
        g_att[base + d] = __float2half_rn(acc[d] * rl);
}

// ---------------- launch ----------------
extern "C" void kernel_launch(void* const* d_in, const int* in_sizes, int n_in,
                              void* d_out, int out_size)
{
    const float* audio   = (const float*)d_in[0];
    const float* log_k   = (const float*)d_in[2];
    const float* lin_w   = (const float*)d_in[3];
    const float* conv1_w = (const float*)d_in[4];
    const float* conv1_b = (const float*)d_in[5];
    const float* conv2_w = (const float*)d_in[6];
    const float* conv2_b = (const float*)d_in[7];
    const float* ln1_w   = (const float*)d_in[8];
    const float* q_w     = (const float*)d_in[9];
    const float* k_w     = (const float*)d_in[10];
    const float* v_w     = (const float*)d_in[11];
    const float* o_w     = (const float*)d_in[12];
    const float* ln2_w   = (const float*)d_in[13];
    const float* fc1_w   = (const float*)d_in[14];
    const float* fc2_w   = (const float*)d_in[15];
    const float* fln_w   = (const float*)d_in[16];

    fp16 *pxn, *px0, *pc1, *ph, *patt, *pffn, *plinw, *pqkvw, *pow_, *pfc1w, *pfc2w, *pw1, *pw2;
    float *px, *pqkv, *ppart;
    cudaGetSymbolAddress((void**)&pxn,   g_xn);
    cudaGetSymbolAddress((void**)&px0,   g_x0);
    cudaGetSymbolAddress((void**)&pc1,   g_c1);
    cudaGetSymbolAddress((void**)&px,    g_x);
    cudaGetSymbolAddress((void**)&pqkv,  g_qkv);
    cudaGetSymbolAddress((void**)&ppart, g_part);
    cudaGetSymbolAddress((void**)&ph,    g_h);
    cudaGetSymbolAddress((void**)&patt,  g_att);
    cudaGetSymbolAddress((void**)&pffn,  g_ffn);
    cudaGetSymbolAddress((void**)&plinw, g_linw);
    cudaGetSymbolAddress((void**)&pqkvw, g_qkvw);
    cudaGetSymbolAddress((void**)&pow_,  g_ow);
    cudaGetSymbolAddress((void**)&pfc1w, g_fc1w);
    cudaGetSymbolAddress((void**)&pfc2w, g_fc2w);
    cudaGetSymbolAddress((void**)&pw1,   g_w1);
    cudaGetSymbolAddress((void**)&pw2,   g_w2);

    float* nullC = 0;
    fp16*  nullP = 0;

    prep_all_kernel<<<dim3(2400, 10), 256>>>(q_w, k_w, v_w, o_w, fc1_w, fc2_w,
                                             lin_w, conv1_w, conv2_w, audio, log_k);
    wmma_gemm_kernel<1, 1, 1, 3><<<dim3(5, NFRM / 128), 128>>>(
        pxn, plinw, nullC, px0, NFRM, 320, 96, 0, 320);
    wmma_conv_kernel<1, 1, 320, 1><<<dim3(10, (T1 / 128) * BB), 128>>>(
        px0, pw1, conv1_b, nullC, pc1, TF, T1, 640);
    wmma_conv_kernel<0, 0, 640, 2><<<dim3(5, (TE / 128) * BB, 2), 128>>>(
        pc1, pw2, conv2_b, ppart, nullP, T1, TE, 320);
    combine_conv_ln_kernel<<<MTOK, HID>>>(ppart, conv2_b, ln1_w, px, ph);

    const int M = MTOK;
    static const int rws[6] = {4, 4, 0, 0, 4, 4};
    for (int i = 0; i < 6; i++) {
        wmma_gemm_kernel<0, 0, 1, 10><<<dim3(10, M / 128), 128>>>(
            ph, pqkvw + (size_t)i * 640 * 320, pqkv, nullP, M, 640, 320, 640, 0);
        attn_kernel<<<dim3(TE / 16, BB), 128>>>(rws[i]);
        wmma_gemm_kernel<0, 0, 2, 5><<<dim3(5, M / 128, 2), 128>>>(
            patt, pow_ + (size_t)i * 320 * 320, ppart, nullP, M, 320, 320, 320, 0);
        combine_ln_kernel<0><<<M, HID>>>(ppart, 2, ln2_w + (size_t)i * HID, px, ph, nullC);
        wmma_gemm_kernel<1, 1, 1, 10><<<dim3(20, M / 128), 128>>>(
            ph, pfc1w + (size_t)i * 1280 * 320, nullC, pffn, M, 1280, 320, 0, 1280);
        wmma_gemm_kernel<0, 0, 4, 10><<<dim3(5, M / 128, 4), 128>>>(
            pffn, pfc2w + (size_t)i * 320 * 1280, ppart, nullP, M, 320, 1280, 320, 0);
        if (i < 5)
            combine_ln_kernel<0><<<M, HID>>>(ppart, 4, ln1_w + (size_t)(i + 1) * HID,
                                             px, ph, nullC);
        else
            combine_ln_kernel<1><<<M, HID>>>(ppart, 4, fln_w, px, nullP, (float*)d_out);
    }
}